// round 10
// baseline (speedup 1.0000x reference)
#include <cuda_runtime.h>
#include <cuda_bf16.h>
#include <math.h>
#include <stdint.h>

// ---- fixed problem shapes ----
#define GG   512
#define NPG  128
#define NN   65536
#define DD   512
#define KC   1024
#define HHID 128
#define TCLS 10

// ---- device scratch ----
static __device__ float g_ct [KC*DD];
static __device__ float g_cs [KC*DD];
static __device__ float g_c1 [KC*DD];
static __device__ float g_ccb[KC*DD];
static __device__ float g_xcb[KC*DD];
static __device__ float g_cbn[KC];
static __device__ int   g_idx[NN];
static __device__ float g_invnx[NN];
static __device__ float g_invnz[NN];
static __device__ __nv_bfloat16 g_xh[NN*DD];
static __device__ __nv_bfloat16 g_xl[NN*DD];
static __device__ __nv_bfloat16 g_ch[KC*DD];
static __device__ __nv_bfloat16 g_cl[KC*DD];
static __device__ __nv_bfloat16 g_cth[KC*DD];
static __device__ __nv_bfloat16 g_ctl[KC*DD];
static __device__ int g_nflag;
static __device__ int g_flag[NN];

// ---- output offsets (floats) ----
#define O_CPRE 0LL
#define O_KPRE 5120LL
#define O_YPRE 10240LL
#define O_AO   15360LL
#define O_AR   8403968LL
#define O_Z    16792576LL
#define O_X    50347008LL
#define O_CD   83901440LL
#define O_CM   84950016LL
#define O_PC   85998592LL
#define O_PX   86260736LL

__device__ __forceinline__ float sigm(float v) { return 1.f / (1.f + expf(-v)); }
__device__ __forceinline__ float sigm10f(float v) { return 1.f / (1.f + __expf(-10.f * v)); }

// ---- portable tensor-core helpers ----
__device__ __forceinline__ uint32_t smem_u32(const void* p) {
    uint32_t a;
    asm("{ .reg .u64 t; cvta.to.shared.u64 t, %1; cvt.u32.u64 %0, t; }" : "=r"(a) : "l"(p));
    return a;
}
__device__ __forceinline__ void mma_bf16(float* d, uint32_t a0, uint32_t a1, uint32_t a2, uint32_t a3,
                                         uint32_t b0, uint32_t b1) {
    asm volatile("mma.sync.aligned.m16n8k16.row.col.f32.bf16.bf16.f32 "
                 "{%0,%1,%2,%3}, {%4,%5,%6,%7}, {%8,%9}, {%0,%1,%2,%3};"
                 : "+f"(d[0]), "+f"(d[1]), "+f"(d[2]), "+f"(d[3])
                 : "r"(a0), "r"(a1), "r"(a2), "r"(a3), "r"(b0), "r"(b1));
}
__device__ __forceinline__ void cp_async16(uint32_t dst, const void* src) {
    asm volatile("cp.async.cg.shared.global [%0], [%1], 16;" :: "r"(dst), "l"(src) : "memory");
}
#define CP_COMMIT()  asm volatile("cp.async.commit_group;" ::: "memory")
#define CP_WAIT(n)   asm volatile("cp.async.wait_group %0;" :: "n"(n) : "memory")

__device__ __forceinline__ uint32_t fkey(float f) {
    uint32_t b = __float_as_uint(f);
    return (b & 0x80000000u) ? ~b : (b | 0x80000000u);
}
__device__ __forceinline__ float funkey(uint32_t k) {
    uint32_t b = (k & 0x80000000u) ? (k & 0x7FFFFFFFu) : ~k;
    return __uint_as_float(b);
}

// shared probe: returns 1 if A-frag middle registers must be swapped
__device__ __forceinline__ int mma_layout_probe(char* sm, int* s_flag) {
    int tid = threadIdx.x, lane = tid & 31, wid = tid >> 5;
    int g = lane >> 2, tg = lane & 3;
    char* Ap = sm;
    char* Bp = sm + 8192;
    if (tid < 256) {
        int r = tid >> 4, k = tid & 15;
        *(__nv_bfloat16*)(Ap + r * 144 + k * 2) = __float2bfloat16((float)(r * 16 + k));
    }
    if (tid < 128) {
        int n = tid >> 4, k = tid & 15;
        *(__nv_bfloat16*)(Bp + n * 144 + k * 2) = __float2bfloat16((n == 0 && k == 0) ? 1.f : 0.f);
    }
    __syncthreads();
    if (wid == 0) {
        uint32_t a0 = *(uint32_t*)(Ap + g * 144 + tg * 4);
        uint32_t a1 = *(uint32_t*)(Ap + (g + 8) * 144 + tg * 4);
        uint32_t a2 = *(uint32_t*)(Ap + g * 144 + 16 + tg * 4);
        uint32_t a3 = *(uint32_t*)(Ap + (g + 8) * 144 + 16 + tg * 4);
        uint32_t b0 = *(uint32_t*)(Bp + g * 144 + tg * 4);
        uint32_t b1 = *(uint32_t*)(Bp + g * 144 + 16 + tg * 4);
        float d[4] = {0.f, 0.f, 0.f, 0.f};
        mma_bf16(d, a0, a1, a2, a3, b0, b1);
        int bad = (tg == 0) && (d[2] != (float)((g + 8) * 16));
        uint32_t anybad = __ballot_sync(~0u, bad);
        if (lane == 0) *s_flag = (anybad != 0) ? 1 : 0;
    }
    __syncthreads();
    int v = *s_flag;
    __syncthreads();
    return v;
}

// ============================================================
// K1: codebook MLP
// ============================================================
__global__ void mlp_kernel(const float* __restrict__ cbin,
                           const float* __restrict__ fc1w, const float* __restrict__ fc1b,
                           const float* __restrict__ fc2w, const float* __restrict__ fc2b) {
    __shared__ float row[DD];
    __shared__ float hs[HHID];
    int k = blockIdx.x, t = threadIdx.x;
    for (int d = t; d < DD; d += 128) row[d] = cbin[(size_t)k*DD + d];
    __syncthreads();
    float acc = fc1b[t];
    const float* w = fc1w + (size_t)t*DD;
    #pragma unroll 8
    for (int d = 0; d < DD; d++) acc += row[d] * w[d];
    hs[t] = sigm(acc);
    __syncthreads();
    for (int d = t; d < DD; d += 128) {
        float a = fc2b[d];
        const float* w2 = fc2w + (size_t)d*HHID;
        #pragma unroll 8
        for (int h = 0; h < HHID; h++) a += hs[h] * w2[h];
        g_ct[(size_t)k*DD + d] = a;
        g_cs[(size_t)k*DD + d] = sigm(a);
    }
}

// ============================================================
// K2: diag / off-diag outputs
// ============================================================
__global__ void diag_kernel(const float* __restrict__ causal, float* __restrict__ out) {
    int i = blockIdx.x;
    size_t base = (size_t)i * KC;
    for (int j = threadIdx.x; j < KC; j += blockDim.x) {
        float c = causal[base + j];
        bool dg = (j == i);
        out[O_CD + base + j] = dg ? c : 0.f;
        out[O_CM + base + j] = dg ? 0.f : c;
    }
}

// ============================================================
// K3: codebook GEMMs
// ============================================================
__global__ __launch_bounds__(256) void gemm_cc(const float* __restrict__ A, int mode) {
    const float* B = (mode == 2) ? g_c1 : g_cs;
    float* C = (mode == 0) ? g_c1 : (mode == 1 ? g_ccb : g_xcb);
    float diag_patch = (mode == 0) ? 0.f : 1.f;
    bool scale = (mode == 1);

    __shared__ __align__(16) float As[16][68];
    __shared__ __align__(16) float Bs[16][68];
    int tid = threadIdx.x, tx = tid & 15, ty = tid >> 4;
    int bm = blockIdx.y * 64, bn = blockIdx.x * 64;
    float acc[4][4] = {};
    for (int k0 = 0; k0 < KC; k0 += 16) {
        #pragma unroll
        for (int p = 0; p < 4; p++) {
            int e = tid + p * 256;
            int r = e >> 4, kk = e & 15;
            int grow = bm + r, gk = k0 + kk;
            As[kk][r] = (grow == gk) ? diag_patch : A[(size_t)grow*KC + gk];
        }
        #pragma unroll
        for (int p = 0; p < 4; p++) {
            int e = tid + p * 256;
            int kk = e >> 6, c = e & 63;
            int gk = k0 + kk;
            float bv = B[(size_t)gk*DD + bn + c];
            if (scale) bv *= A[(size_t)gk*KC + gk];
            Bs[kk][c] = bv;
        }
        __syncthreads();
        #pragma unroll
        for (int kk = 0; kk < 16; kk++) {
            float4 a = *(const float4*)&As[kk][ty*4];
            float4 b = *(const float4*)&Bs[kk][tx*4];
            float av[4] = {a.x, a.y, a.z, a.w};
            float bv[4] = {b.x, b.y, b.z, b.w};
            #pragma unroll
            for (int i = 0; i < 4; i++)
                #pragma unroll
                for (int j = 0; j < 4; j++)
                    acc[i][j] += av[i] * bv[j];
        }
        __syncthreads();
    }
    #pragma unroll
    for (int i = 0; i < 4; i++) {
        float4 v = make_float4(acc[i][0], acc[i][1], acc[i][2], acc[i][3]);
        *(float4*)&C[(size_t)(bm + ty*4 + i)*DD + bn + tx*4] = v;
    }
}

// ============================================================
// K4: g_cbn + reset flag counter
// ============================================================
__global__ void cbn_kernel() {
    if (blockIdx.x == 0 && threadIdx.x == 0) g_nflag = 0;
    int k = blockIdx.x;
    float s = 0.f;
    for (int d = threadIdx.x; d < DD; d += 128) {
        float v = g_ccb[(size_t)k*DD + d];
        s += v * v;
    }
    #pragma unroll
    for (int off = 16; off; off >>= 1) s += __shfl_xor_sync(~0u, s, off);
    __shared__ float red[4];
    if ((threadIdx.x & 31) == 0) red[threadIdx.x >> 5] = s;
    __syncthreads();
    if (threadIdx.x == 0) g_cbn[k] = red[0] + red[1] + red[2] + red[3];
}

// ============================================================
// K4b: fp32 -> split bf16 (hi + exact residual-lo)
// ============================================================
#define X8   (NN*DD/8)        // 4194304
#define C8   (KC*DD/8)        // 65536

__device__ __forceinline__ void split8(const float4* s, __nv_bfloat16* dh, __nv_bfloat16* dl, size_t j) {
    float4 f0 = s[0], f1 = s[1];
    float f[8] = {f0.x, f0.y, f0.z, f0.w, f1.x, f1.y, f1.z, f1.w};
    unsigned short hb[8], lb[8];
    #pragma unroll
    for (int e = 0; e < 8; e++) {
        __nv_bfloat16 h = __float2bfloat16(f[e]);
        float r = f[e] - __bfloat162float(h);
        __nv_bfloat16 l = __float2bfloat16(r);
        hb[e] = __nv_bfloat16_raw(h).x;
        lb[e] = __nv_bfloat16_raw(l).x;
    }
    ((uint4*)dh)[j] = make_uint4(hb[0]|(hb[1]<<16), hb[2]|(hb[3]<<16), hb[4]|(hb[5]<<16), hb[6]|(hb[7]<<16));
    ((uint4*)dl)[j] = make_uint4(lb[0]|(lb[1]<<16), lb[2]|(lb[3]<<16), lb[4]|(lb[5]<<16), lb[6]|(lb[7]<<16));
}

__global__ void convert_x(const float* __restrict__ x) {
    size_t i = (size_t)blockIdx.x * blockDim.x + threadIdx.x;
    if (i >= X8) return;
    split8((const float4*)x + i*2, g_xh, g_xl, i);
}
__global__ void convert_cbct() {
    size_t i = (size_t)blockIdx.x * blockDim.x + threadIdx.x;
    if (i >= 2 * C8) return;
    if (i < C8) split8((const float4*)g_ccb + i*2, g_ch, g_cl, i);
    else { size_t j = i - C8; split8((const float4*)g_ct + j*2, g_cth, g_ctl, j); }
}

// ============================================================
// K5: 3-pass split-bf16 tensor-core argmin (race-free)
// ============================================================
#define RSTRIDE   144
#define SUB_TB    (128 * RSTRIDE)          // 18432
#define OFF_XH    0
#define OFF_XL    SUB_TB
#define OFF_CH    (2 * SUB_TB)
#define OFF_CL    (3 * SUB_TB)
#define STAGE_B3  (4 * SUB_TB)             // 73728
#define OFF_CBN3  (2 * STAGE_B3)           // 147456
#define SM3_DYN   (OFF_CBN3 + KC * 4)      // 151552
#define AM_MARGIN 0.35f

__device__ __forceinline__ void stage_load3(uint32_t dst, int node0, int c0, int kt) {
    int tid = threadIdx.x;
    const __nv_bfloat16* srcs[4] = {
        g_xh + (size_t)node0 * DD, g_xl + (size_t)node0 * DD,
        g_ch + (size_t)c0 * DD,    g_cl + (size_t)c0 * DD };
    #pragma unroll
    for (int s = 0; s < 4; s++) {
        uint32_t d = dst + (uint32_t)s * SUB_TB;
        const __nv_bfloat16* src = srcs[s] + kt * 64;
        #pragma unroll
        for (int it = 0; it < 4; it++) {
            int idx = tid + it * 256;
            int row = idx >> 3, c8 = idx & 7;
            cp_async16(d + (uint32_t)row * RSTRIDE + (uint32_t)c8 * 16,
                       src + (size_t)row * DD + c8 * 8);
        }
    }
}

__global__ __launch_bounds__(256) void argmin_mma3() {
    extern __shared__ char sm[];
    float* scbn = (float*)(sm + OFF_CBN3);
    __shared__ int s_v1;

    int tid = threadIdx.x, lane = tid & 31, wid = tid >> 5;
    int g = lane >> 2, tg = lane & 3;
    int node0 = blockIdx.x * 128;

    int v1 = mma_layout_probe(sm, &s_v1);
    uint32_t offA1 = v1 ? 16u : (uint32_t)(8 * RSTRIDE);
    uint32_t offA2 = v1 ? (uint32_t)(8 * RSTRIDE) : 16u;

    for (int i = tid; i < KC; i += 256) scbn[i] = g_cbn[i];

    uint32_t smb = smem_u32(sm);
    stage_load3(smb, node0, 0, 0);
    CP_COMMIT();

    unsigned long long rs1[2], rs2[2];
    rs1[0] = rs1[1] = rs2[0] = rs2[1] = ~0ULL;

    float acc[16][4];

    for (int t = 0; t < 64; t++) {
        int c = t >> 3, kt = t & 7;
        if (kt == 0) {
            #pragma unroll
            for (int nf = 0; nf < 16; nf++)
                #pragma unroll
                for (int q = 0; q < 4; q++) acc[nf][q] = 0.f;
        }
        if (t < 63) {
            int tn = t + 1;
            stage_load3(smb + (uint32_t)(tn & 1) * STAGE_B3, node0, (tn >> 3) * 128, tn & 7);
            CP_COMMIT();
            CP_WAIT(1);
        } else {
            CP_WAIT(0);
        }
        __syncthreads();

        const char* St = sm + (size_t)(t & 1) * STAGE_B3;
        const char* Axh = St + OFF_XH + (size_t)(wid * 16 + g) * RSTRIDE;
        const char* Axl = St + OFF_XL + (size_t)(wid * 16 + g) * RSTRIDE;
        const char* Bch = St + OFF_CH + (size_t)g * RSTRIDE;
        const char* Bcl = St + OFF_CL + (size_t)g * RSTRIDE;
        #pragma unroll
        for (int ks = 0; ks < 4; ks++) {
            int koff = (ks * 16 + tg * 2) * 2;
            uint32_t h0 = *(const uint32_t*)(Axh + koff);
            uint32_t h1 = *(const uint32_t*)(Axh + koff + offA1);
            uint32_t h2 = *(const uint32_t*)(Axh + koff + offA2);
            uint32_t h3 = *(const uint32_t*)(Axh + koff + 8 * RSTRIDE + 16);
            uint32_t l0 = *(const uint32_t*)(Axl + koff);
            uint32_t l1 = *(const uint32_t*)(Axl + koff + offA1);
            uint32_t l2 = *(const uint32_t*)(Axl + koff + offA2);
            uint32_t l3 = *(const uint32_t*)(Axl + koff + 8 * RSTRIDE + 16);
            int kb = ks * 32 + tg * 4;
            #pragma unroll
            for (int nf = 0; nf < 16; nf++) {
                size_t bro = (size_t)(nf * 8) * RSTRIDE + kb;
                uint32_t bh0 = *(const uint32_t*)(Bch + bro);
                uint32_t bh1 = *(const uint32_t*)(Bch + bro + 16);
                uint32_t bl0 = *(const uint32_t*)(Bcl + bro);
                uint32_t bl1 = *(const uint32_t*)(Bcl + bro + 16);
                mma_bf16(acc[nf], h0, h1, h2, h3, bh0, bh1);
                mma_bf16(acc[nf], h0, h1, h2, h3, bl0, bl1);
                mma_bf16(acc[nf], l0, l1, l2, l3, bh0, bh1);
            }
        }
        __syncthreads();

        if (kt == 7) {
            #pragma unroll
            for (int h = 0; h < 2; h++) {
                unsigned long long s1 = ~0ULL, s2 = ~0ULL;
                #pragma unroll
                for (int nf = 0; nf < 16; nf++) {
                    #pragma unroll
                    for (int q = 0; q < 2; q++) {
                        int code = c * 128 + nf * 8 + tg * 2 + q;
                        float sc = scbn[code] - 2.f * acc[nf][h * 2 + q];
                        unsigned long long p = ((unsigned long long)fkey(sc) << 32) | (uint32_t)code;
                        if (p < s1) { s2 = s1; s1 = p; }
                        else if (p < s2) s2 = p;
                    }
                }
                #pragma unroll
                for (int off = 1; off <= 2; off <<= 1) {
                    unsigned long long o1 = __shfl_xor_sync(~0u, s1, off);
                    unsigned long long o2 = __shfl_xor_sync(~0u, s2, off);
                    if (o1 < s1) { s2 = (s1 < o2) ? s1 : o2; s1 = o1; }
                    else         { s2 = (s2 < o1) ? s2 : o1; }
                }
                if (s1 < rs1[h]) {
                    rs2[h] = (rs1[h] < s2) ? rs1[h] : s2;
                    rs1[h] = s1;
                } else {
                    rs2[h] = (rs2[h] < s1) ? rs2[h] : s1;
                }
            }
        }
    }

    if (tg == 0) {
        #pragma unroll
        for (int h = 0; h < 2; h++) {
            int node = node0 + wid * 16 + h * 8 + g;
            g_idx[node] = (int)(rs1[h] & 0xFFFFFFFFu);
            float f1 = funkey((uint32_t)(rs1[h] >> 32));
            float f2 = funkey((uint32_t)(rs2[h] >> 32));
            if (!(f2 - f1 >= AM_MARGIN)) {
                int p = atomicAdd(&g_nflag, 1);
                g_flag[p] = node;
            }
        }
    }
}

// ============================================================
// K5b: exact fp32 refinement
// ============================================================
__global__ __launch_bounds__(256) void refine3(const float* __restrict__ x) {
    __shared__ __align__(16) float xs[DD];
    __shared__ unsigned long long sbest;
    int tid = threadIdx.x;
    int nf = g_nflag;
    for (int f = blockIdx.x; f < nf; f += gridDim.x) {
        int node = g_flag[f];
        if (tid < 128) ((float4*)xs)[tid] = ((const float4*)x)[(size_t)node * 128 + tid];
        if (tid == 0) sbest = ~0ULL;
        __syncthreads();
        unsigned long long best = ~0ULL;
        #pragma unroll
        for (int cc = 0; cc < 4; cc++) {
            int code = tid + cc * 256;
            const float4* cb = (const float4*)(g_ccb + (size_t)code * DD);
            float dot = 0.f;
            #pragma unroll 8
            for (int q = 0; q < 128; q++) {
                float4 a = ((const float4*)xs)[q], b = cb[q];
                dot += a.x * b.x + a.y * b.y + a.z * b.z + a.w * b.w;
            }
            float sc = g_cbn[code] - 2.f * dot;
            unsigned long long p = ((unsigned long long)fkey(sc) << 32) | (uint32_t)code;
            if (p < best) best = p;
        }
        atomicMin(&sbest, best);
        __syncthreads();
        if (tid == 0) g_idx[node] = (int)(sbest & 0xFFFFFFFFu);
        __syncthreads();
    }
}

// ============================================================
// K6: per node: x copy, z gather, inv norms
// ============================================================
__global__ void node_kernel(const float* __restrict__ x, float* __restrict__ out) {
    int n = blockIdx.x, t = threadIdx.x;
    float4 xv = ((const float4*)x)[(size_t)n*128 + t];
    ((float4*)(out + O_X))[(size_t)n*128 + t] = xv;
    int code = g_idx[n];
    float4 zv = ((const float4*)g_ct)[(size_t)code*128 + t];
    ((float4*)(out + O_Z))[(size_t)n*128 + t] = zv;
    float sx = xv.x*xv.x + xv.y*xv.y + xv.z*xv.z + xv.w*xv.w;
    float sz = zv.x*zv.x + zv.y*zv.y + zv.z*zv.z + zv.w*zv.w;
    #pragma unroll
    for (int off = 16; off; off >>= 1) {
        sx += __shfl_xor_sync(~0u, sx, off);
        sz += __shfl_xor_sync(~0u, sz, off);
    }
    __shared__ float rx[4], rz[4];
    if ((t & 31) == 0) { rx[t >> 5] = sx; rz[t >> 5] = sz; }
    __syncthreads();
    if (t == 0) {
        float nx = sqrtf(rx[0] + rx[1] + rx[2] + rx[3]);
        float nz = sqrtf(rz[0] + rz[1] + rz[2] + rz[3]);
        g_invnx[n] = 1.f / fmaxf(nx, 1e-12f);
        g_invnz[n] = 1.f / fmaxf(nz, 1e-12f);
    }
}

// ============================================================
// K7: pooled means + classifier heads
// ============================================================
__global__ __launch_bounds__(256) void pool_kernel(const float* __restrict__ x,
                                                   const float* __restrict__ clsw,
                                                   const float* __restrict__ clsb,
                                                   float* __restrict__ out) {
    int g = blockIdx.x, t = threadIdx.x;
    __shared__ int idxs[NPG];
    __shared__ float sp[3][DD];
    if (t < NPG) idxs[t] = g_idx[g*NPG + t];
    __syncthreads();
    for (int d = t; d < DD; d += 256) {
        float ax = 0.f, ac = 0.f, ak = 0.f;
        #pragma unroll 4
        for (int nn = 0; nn < NPG; nn++) {
            ax += x[(size_t)(g*NPG + nn)*DD + d];
            int c = idxs[nn];
            ac += g_ccb[(size_t)c*DD + d];
            ak += g_xcb[(size_t)c*DD + d];
        }
        float px = ax * (1.f/128.f);
        float pc = px + ac * (1.f/128.f);
        float pk = ak * (1.f/128.f);
        out[O_PX + (size_t)g*DD + d] = px;
        out[O_PC + (size_t)g*DD + d] = pc;
        sp[0][d] = pc; sp[1][d] = pk; sp[2][d] = px;
    }
    __syncthreads();
    int lane = t & 31, w = t >> 5;
    for (int job = w; job < 30; job += 8) {
        int vec = job / 10, cc = job % 10;
        float a = 0.f;
        for (int d = lane; d < DD; d += 32) a += sp[vec][d] * clsw[(size_t)cc*DD + d];
        #pragma unroll
        for (int off = 16; off; off >>= 1) a += __shfl_xor_sync(~0u, a, off);
        if (lane == 0) {
            long long base = (vec == 0) ? O_CPRE : (vec == 1 ? O_KPRE : O_YPRE);
            out[base + (size_t)g*TCLS + cc] = a + clsb[cc];
        }
    }
}

// ============================================================
// K8: adjacency via 3-pass split-bf16 mma (Gram), normalize in epilogue.
// ============================================================
#define AJ_STAGE  (2 * SUB_TB)             // 36864
#define AJ_DYN    (2 * AJ_STAGE)           // 73728

__device__ __forceinline__ void adj_stage(uint32_t dst, const __nv_bfloat16* baseh,
                                          const __nv_bfloat16* basel, const int* idx_s,
                                          int node0, int mode, int kt) {
    int tid = threadIdx.x;
    #pragma unroll
    for (int it = 0; it < 8; it++) {
        int e = tid + it * 256;
        int sub = e >> 10;
        int w = e & 1023;
        int row = w >> 3, c8 = w & 7;
        const __nv_bfloat16* src = sub ? basel : baseh;
        size_t roff = mode ? (size_t)idx_s[row] : (size_t)(node0 + row);
        cp_async16(dst + (uint32_t)sub * SUB_TB + (uint32_t)row * RSTRIDE + (uint32_t)c8 * 16,
                   src + roff * DD + kt * 64 + c8 * 8);
    }
}

__global__ __launch_bounds__(256) void adj_mma(float* __restrict__ out) {
    extern __shared__ char sm[];
    __shared__ int s_v1;
    __shared__ int idx_s[NPG];
    __shared__ float invn_s[NPG];

    int tid = threadIdx.x, lane = tid & 31, wid = tid >> 5;
    int g = lane >> 2, tg = lane & 3;
    int b = blockIdx.x;
    int mode = b >> 9;
    int gr = b & 511;
    int node0 = gr * 128;

    int v1 = mma_layout_probe(sm, &s_v1);
    uint32_t offA1 = v1 ? 16u : (uint32_t)(8 * RSTRIDE);
    uint32_t offA2 = v1 ? (uint32_t)(8 * RSTRIDE) : 16u;

    if (tid < NPG) {
        idx_s[tid]  = g_idx[node0 + tid];
        invn_s[tid] = mode ? g_invnz[node0 + tid] : g_invnx[node0 + tid];
    }
    __syncthreads();

    const __nv_bfloat16* baseh = mode ? g_cth : g_xh;
    const __nv_bfloat16* basel = mode ? g_ctl : g_xl;
    uint32_t smb = smem_u32(sm);

    adj_stage(smb, baseh, basel, idx_s, node0, mode, 0);
    CP_COMMIT();

    float acc[16][4];
    #pragma unroll
    for (int nf = 0; nf < 16; nf++)
        #pragma unroll
        for (int q = 0; q < 4; q++) acc[nf][q] = 0.f;

    for (int kt = 0; kt < 8; kt++) {
        if (kt < 7) {
            adj_stage(smb + (uint32_t)((kt + 1) & 1) * AJ_STAGE, baseh, basel, idx_s, node0, mode, kt + 1);
            CP_COMMIT();
            CP_WAIT(1);
        } else {
            CP_WAIT(0);
        }
        __syncthreads();

        const char* St = sm + (size_t)(kt & 1) * AJ_STAGE;
        const char* Ah = St + (size_t)(wid * 16 + g) * RSTRIDE;
        const char* Al = St + SUB_TB + (size_t)(wid * 16 + g) * RSTRIDE;
        const char* Bh = St;
        const char* Bl = St + SUB_TB;
        #pragma unroll
        for (int ks = 0; ks < 4; ks++) {
            int koff = (ks * 16 + tg * 2) * 2;
            uint32_t h0 = *(const uint32_t*)(Ah + koff);
            uint32_t h1 = *(const uint32_t*)(Ah + koff + offA1);
            uint32_t h2 = *(const uint32_t*)(Ah + koff + offA2);
            uint32_t h3 = *(const uint32_t*)(Ah + koff + 8 * RSTRIDE + 16);
            uint32_t l0 = *(const uint32_t*)(Al + koff);
            uint32_t l1 = *(const uint32_t*)(Al + koff + offA1);
            uint32_t l2 = *(const uint32_t*)(Al + koff + offA2);
            uint32_t l3 = *(const uint32_t*)(Al + koff + 8 * RSTRIDE + 16);
            int kb = ks * 32 + tg * 4;
            #pragma unroll
            for (int nf = 0; nf < 16; nf++) {
                size_t bro = (size_t)(nf * 8 + g) * RSTRIDE + kb;
                uint32_t bh0 = *(const uint32_t*)(Bh + bro);
                uint32_t bh1 = *(const uint32_t*)(Bh + bro + 16);
                uint32_t bl0 = *(const uint32_t*)(Bl + bro);
                uint32_t bl1 = *(const uint32_t*)(Bl + bro + 16);
                mma_bf16(acc[nf], h0, h1, h2, h3, bh0, bh1);
                mma_bf16(acc[nf], h0, h1, h2, h3, bl0, bl1);
                mma_bf16(acc[nf], l0, l1, l2, l3, bh0, bh1);
            }
        }
        __syncthreads();
    }

    float* dst = out + (mode ? O_AR : O_AO) + (size_t)gr * (NPG * NPG);
    #pragma unroll
    for (int h = 0; h < 2; h++) {
        int r = wid * 16 + h * 8 + g;
        float invr = invn_s[r];
        #pragma unroll
        for (int nf = 0; nf < 16; nf++) {
            #pragma unroll
            for (int q = 0; q < 2; q++) {
                int c = nf * 8 + tg * 2 + q;
                dst[(size_t)r * NPG + c] = sigm10f(acc[nf][h * 2 + q] * invr * invn_s[c]);
            }
        }
    }
}

// ============================================================
extern "C" void kernel_launch(void* const* d_in, const int* in_sizes, int n_in,
                              void* d_out, int out_size) {
    const float* x      = (const float*)d_in[0];
    const float* cbin   = (const float*)d_in[2];
    const float* fc1w   = (const float*)d_in[3];
    const float* fc1b   = (const float*)d_in[4];
    const float* fc2w   = (const float*)d_in[5];
    const float* fc2b   = (const float*)d_in[6];
    const float* causal = (const float*)d_in[7];
    const float* clsw   = (const float*)d_in[8];
    const float* clsb   = (const float*)d_in[9];
    float* out = (float*)d_out;

    // one-time side stream + events (no device memory involved)
    static cudaStream_t s2 = nullptr;
    static cudaEvent_t ev0, ev1, ev2, ev3, evX, evR;
    if (!s2) {
        cudaStreamCreateWithFlags(&s2, cudaStreamNonBlocking);
        cudaEventCreateWithFlags(&ev0, cudaEventDisableTiming);
        cudaEventCreateWithFlags(&ev1, cudaEventDisableTiming);
        cudaEventCreateWithFlags(&ev2, cudaEventDisableTiming);
        cudaEventCreateWithFlags(&ev3, cudaEventDisableTiming);
        cudaEventCreateWithFlags(&evX, cudaEventDisableTiming);
        cudaEventCreateWithFlags(&evR, cudaEventDisableTiming);
        cudaFuncSetAttribute(argmin_mma3, cudaFuncAttributeMaxDynamicSharedMemorySize, SM3_DYN);
        cudaFuncSetAttribute(adj_mma,     cudaFuncAttributeMaxDynamicSharedMemorySize, AJ_DYN);
    }

    // fork s2 from the captured origin stream
    cudaEventRecord(ev0, 0);
    cudaStreamWaitEvent(s2, ev0, 0);

    // s2: convert x (needs only x)
    convert_x<<<X8 / 256, 256, 0, s2>>>(x);
    cudaEventRecord(evX, s2);

    // default: mlp -> gemm1 (critical path)
    mlp_kernel<<<KC, 128>>>(cbin, fc1w, fc1b, fc2w, fc2b);
    cudaEventRecord(ev1, 0);

    // s2: after mlp -> diag, gemm0, gemm2 (independent of argmin chain)
    cudaStreamWaitEvent(s2, ev1, 0);
    diag_kernel<<<KC, 256, 0, s2>>>(causal, out);
    gemm_cc<<<dim3(8, 16), 256, 0, s2>>>(causal, 0);   // c1
    gemm_cc<<<dim3(8, 16), 256, 0, s2>>>(causal, 2);   // counter_cb
    cudaEventRecord(ev2, s2);

    // default: gemm1 -> cbn -> convert(cb,ct) -> argmin -> refine
    gemm_cc<<<dim3(8, 16), 256>>>(causal, 1);           // causal_cb
    cbn_kernel<<<KC, 128>>>();
    convert_cbct<<<(2 * C8) / 256, 256>>>();
    cudaStreamWaitEvent(0, evX, 0);                     // x splits ready
    argmin_mma3<<<NN / 128, 256, SM3_DYN>>>();
    refine3<<<256, 256>>>(x);
    cudaEventRecord(evR, 0);                            // g_idx final

    // default: node -> adj;  s2: pool (hidden under adj)
    node_kernel<<<NN, 128>>>(x, out);
    cudaStreamWaitEvent(s2, evR, 0);                    // idx + (ev2 implicit: same stream)
    pool_kernel<<<GG, 256, 0, s2>>>(x, clsw, clsb, out);
    cudaEventRecord(ev3, s2);
    adj_mma<<<2 * GG, 256, AJ_DYN>>>(out);

    // join s2 back into origin before capture ends
    cudaStreamWaitEvent(0, ev2, 0);
    cudaStreamWaitEvent(0, ev3, 0);
}

// round 12
// speedup vs baseline: 1.2998x; 1.2998x over previous
#include <cuda_runtime.h>
#include <cuda_bf16.h>
#include <cuda_fp16.h>
#include <math.h>
#include <stdint.h>

// ---- fixed problem shapes ----
#define GG   512
#define NPG  128
#define NN   65536
#define DD   512
#define KC   1024
#define HHID 128
#define TCLS 10

// ---- device scratch ----
static __device__ float g_ct [KC*DD];
static __device__ float g_cs [KC*DD];
static __device__ float g_c1 [KC*DD];
static __device__ float g_ccb[KC*DD];
static __device__ float g_xcb[KC*DD];
static __device__ float g_cbn[KC];
static __device__ int   g_idx[NN];
static __device__ float g_invnx[NN];
static __device__ float g_invnz[NN];
static __device__ __nv_bfloat16 g_xh[NN*DD];
static __device__ __nv_bfloat16 g_xl[NN*DD];
static __device__ __nv_bfloat16 g_ch[KC*DD];
static __device__ __nv_bfloat16 g_cl[KC*DD];
static __device__ __half g_xf [NN*DD];
static __device__ __half g_ctf[KC*DD];
static __device__ int g_nflag;
static __device__ int g_flag[NN];

// ---- output offsets (floats) ----
#define O_CPRE 0LL
#define O_KPRE 5120LL
#define O_YPRE 10240LL
#define O_AO   15360LL
#define O_AR   8403968LL
#define O_Z    16792576LL
#define O_X    50347008LL
#define O_CD   83901440LL
#define O_CM   84950016LL
#define O_PC   85998592LL
#define O_PX   86260736LL

__device__ __forceinline__ float sigm(float v) { return 1.f / (1.f + expf(-v)); }
__device__ __forceinline__ float sigm10f(float v) { return 1.f / (1.f + __expf(-10.f * v)); }

// ---- portable tensor-core helpers ----
__device__ __forceinline__ uint32_t smem_u32(const void* p) {
    uint32_t a;
    asm("{ .reg .u64 t; cvta.to.shared.u64 t, %1; cvt.u32.u64 %0, t; }" : "=r"(a) : "l"(p));
    return a;
}
__device__ __forceinline__ void mma_bf16(float* d, uint32_t a0, uint32_t a1, uint32_t a2, uint32_t a3,
                                         uint32_t b0, uint32_t b1) {
    asm volatile("mma.sync.aligned.m16n8k16.row.col.f32.bf16.bf16.f32 "
                 "{%0,%1,%2,%3}, {%4,%5,%6,%7}, {%8,%9}, {%0,%1,%2,%3};"
                 : "+f"(d[0]), "+f"(d[1]), "+f"(d[2]), "+f"(d[3])
                 : "r"(a0), "r"(a1), "r"(a2), "r"(a3), "r"(b0), "r"(b1));
}
__device__ __forceinline__ void mma_f16(float* d, uint32_t a0, uint32_t a1, uint32_t a2, uint32_t a3,
                                        uint32_t b0, uint32_t b1) {
    asm volatile("mma.sync.aligned.m16n8k16.row.col.f32.f16.f16.f32 "
                 "{%0,%1,%2,%3}, {%4,%5,%6,%7}, {%8,%9}, {%0,%1,%2,%3};"
                 : "+f"(d[0]), "+f"(d[1]), "+f"(d[2]), "+f"(d[3])
                 : "r"(a0), "r"(a1), "r"(a2), "r"(a3), "r"(b0), "r"(b1));
}
__device__ __forceinline__ void cp_async16(uint32_t dst, const void* src) {
    asm volatile("cp.async.cg.shared.global [%0], [%1], 16;" :: "r"(dst), "l"(src) : "memory");
}
#define CP_COMMIT()  asm volatile("cp.async.commit_group;" ::: "memory")
#define CP_WAIT(n)   asm volatile("cp.async.wait_group %0;" :: "n"(n) : "memory")

__device__ __forceinline__ uint32_t fkey(float f) {
    uint32_t b = __float_as_uint(f);
    return (b & 0x80000000u) ? ~b : (b | 0x80000000u);
}
__device__ __forceinline__ float funkey(uint32_t k) {
    uint32_t b = (k & 0x80000000u) ? (k & 0x7FFFFFFFu) : ~k;
    return __uint_as_float(b);
}

// shared probe: returns 1 if A-frag middle registers must be swapped
// (fragment layout is identical for f16 and bf16 m16n8k16)
__device__ __forceinline__ int mma_layout_probe(char* sm, int* s_flag) {
    int tid = threadIdx.x, lane = tid & 31, wid = tid >> 5;
    int g = lane >> 2, tg = lane & 3;
    char* Ap = sm;
    char* Bp = sm + 8192;
    if (tid < 256) {
        int r = tid >> 4, k = tid & 15;
        *(__nv_bfloat16*)(Ap + r * 144 + k * 2) = __float2bfloat16((float)(r * 16 + k));
    }
    if (tid < 128) {
        int n = tid >> 4, k = tid & 15;
        *(__nv_bfloat16*)(Bp + n * 144 + k * 2) = __float2bfloat16((n == 0 && k == 0) ? 1.f : 0.f);
    }
    __syncthreads();
    if (wid == 0) {
        uint32_t a0 = *(uint32_t*)(Ap + g * 144 + tg * 4);
        uint32_t a1 = *(uint32_t*)(Ap + (g + 8) * 144 + tg * 4);
        uint32_t a2 = *(uint32_t*)(Ap + g * 144 + 16 + tg * 4);
        uint32_t a3 = *(uint32_t*)(Ap + (g + 8) * 144 + 16 + tg * 4);
        uint32_t b0 = *(uint32_t*)(Bp + g * 144 + tg * 4);
        uint32_t b1 = *(uint32_t*)(Bp + g * 144 + 16 + tg * 4);
        float d[4] = {0.f, 0.f, 0.f, 0.f};
        mma_bf16(d, a0, a1, a2, a3, b0, b1);
        int bad = (tg == 0) && (d[2] != (float)((g + 8) * 16));
        uint32_t anybad = __ballot_sync(~0u, bad);
        if (lane == 0) *s_flag = (anybad != 0) ? 1 : 0;
    }
    __syncthreads();
    int v = *s_flag;
    __syncthreads();
    return v;
}

// ============================================================
// K1: codebook MLP
// ============================================================
__global__ void mlp_kernel(const float* __restrict__ cbin,
                           const float* __restrict__ fc1w, const float* __restrict__ fc1b,
                           const float* __restrict__ fc2w, const float* __restrict__ fc2b) {
    __shared__ float row[DD];
    __shared__ float hs[HHID];
    int k = blockIdx.x, t = threadIdx.x;
    for (int d = t; d < DD; d += 128) row[d] = cbin[(size_t)k*DD + d];
    __syncthreads();
    float acc = fc1b[t];
    const float* w = fc1w + (size_t)t*DD;
    #pragma unroll 8
    for (int d = 0; d < DD; d++) acc += row[d] * w[d];
    hs[t] = sigm(acc);
    __syncthreads();
    for (int d = t; d < DD; d += 128) {
        float a = fc2b[d];
        const float* w2 = fc2w + (size_t)d*HHID;
        #pragma unroll 8
        for (int h = 0; h < HHID; h++) a += hs[h] * w2[h];
        g_ct[(size_t)k*DD + d] = a;
        g_cs[(size_t)k*DD + d] = sigm(a);
    }
}

// ============================================================
// K2: diag / off-diag outputs
// ============================================================
__global__ void diag_kernel(const float* __restrict__ causal, float* __restrict__ out) {
    int i = blockIdx.x;
    size_t base = (size_t)i * KC;
    for (int j = threadIdx.x; j < KC; j += blockDim.x) {
        float c = causal[base + j];
        bool dg = (j == i);
        out[O_CD + base + j] = dg ? c : 0.f;
        out[O_CM + base + j] = dg ? 0.f : c;
    }
}

// ============================================================
// K3: codebook GEMMs; mode 3 = fused modes 0+1 in one grid (8,32)
// ============================================================
__global__ __launch_bounds__(256) void gemm_cc(const float* __restrict__ A, int mode) {
    int by = blockIdx.y;
    if (mode == 3) { mode = (by < 16) ? 0 : 1; by &= 15; }
    const float* B = (mode == 2) ? g_c1 : g_cs;
    float* C = (mode == 0) ? g_c1 : (mode == 1 ? g_ccb : g_xcb);
    float diag_patch = (mode == 0) ? 0.f : 1.f;
    bool scale = (mode == 1);

    __shared__ __align__(16) float As[16][68];
    __shared__ __align__(16) float Bs[16][68];
    int tid = threadIdx.x, tx = tid & 15, ty = tid >> 4;
    int bm = by * 64, bn = blockIdx.x * 64;
    float acc[4][4] = {};
    for (int k0 = 0; k0 < KC; k0 += 16) {
        #pragma unroll
        for (int p = 0; p < 4; p++) {
            int e = tid + p * 256;
            int r = e >> 4, kk = e & 15;
            int grow = bm + r, gk = k0 + kk;
            As[kk][r] = (grow == gk) ? diag_patch : A[(size_t)grow*KC + gk];
        }
        #pragma unroll
        for (int p = 0; p < 4; p++) {
            int e = tid + p * 256;
            int kk = e >> 6, c = e & 63;
            int gk = k0 + kk;
            float bv = B[(size_t)gk*DD + bn + c];
            if (scale) bv *= A[(size_t)gk*KC + gk];
            Bs[kk][c] = bv;
        }
        __syncthreads();
        #pragma unroll
        for (int kk = 0; kk < 16; kk++) {
            float4 a = *(const float4*)&As[kk][ty*4];
            float4 b = *(const float4*)&Bs[kk][tx*4];
            float av[4] = {a.x, a.y, a.z, a.w};
            float bv[4] = {b.x, b.y, b.z, b.w};
            #pragma unroll
            for (int i = 0; i < 4; i++)
                #pragma unroll
                for (int j = 0; j < 4; j++)
                    acc[i][j] += av[i] * bv[j];
        }
        __syncthreads();
    }
    #pragma unroll
    for (int i = 0; i < 4; i++) {
        float4 v = make_float4(acc[i][0], acc[i][1], acc[i][2], acc[i][3]);
        *(float4*)&C[(size_t)(bm + ty*4 + i)*DD + bn + tx*4] = v;
    }
}

// ============================================================
// K4: g_cbn + reset flag counter
// ============================================================
__global__ void cbn_kernel() {
    if (blockIdx.x == 0 && threadIdx.x == 0) g_nflag = 0;
    int k = blockIdx.x;
    float s = 0.f;
    for (int d = threadIdx.x; d < DD; d += 128) {
        float v = g_ccb[(size_t)k*DD + d];
        s += v * v;
    }
    #pragma unroll
    for (int off = 16; off; off >>= 1) s += __shfl_xor_sync(~0u, s, off);
    __shared__ float red[4];
    if ((threadIdx.x & 31) == 0) red[threadIdx.x >> 5] = s;
    __syncthreads();
    if (threadIdx.x == 0) g_cbn[k] = red[0] + red[1] + red[2] + red[3];
}

// ============================================================
// K4b: conversions
// ============================================================
#define X8   (NN*DD/8)        // 4194304
#define C8   (KC*DD/8)        // 65536

__device__ __forceinline__ void split8(const float4* s, __nv_bfloat16* dh, __nv_bfloat16* dl, size_t j) {
    float4 f0 = s[0], f1 = s[1];
    float f[8] = {f0.x, f0.y, f0.z, f0.w, f1.x, f1.y, f1.z, f1.w};
    unsigned short hb[8], lb[8];
    #pragma unroll
    for (int e = 0; e < 8; e++) {
        __nv_bfloat16 h = __float2bfloat16(f[e]);
        float r = f[e] - __bfloat162float(h);
        __nv_bfloat16 l = __float2bfloat16(r);
        hb[e] = __nv_bfloat16_raw(h).x;
        lb[e] = __nv_bfloat16_raw(l).x;
    }
    ((uint4*)dh)[j] = make_uint4(hb[0]|(hb[1]<<16), hb[2]|(hb[3]<<16), hb[4]|(hb[5]<<16), hb[6]|(hb[7]<<16));
    ((uint4*)dl)[j] = make_uint4(lb[0]|(lb[1]<<16), lb[2]|(lb[3]<<16), lb[4]|(lb[5]<<16), lb[6]|(lb[7]<<16));
}
__device__ __forceinline__ void pack_f16(const float4* s, __half* df, size_t j) {
    float4 f0 = s[0], f1 = s[1];
    __half2 h0 = __floats2half2_rn(f0.x, f0.y);
    __half2 h1 = __floats2half2_rn(f0.z, f0.w);
    __half2 h2 = __floats2half2_rn(f1.x, f1.y);
    __half2 h3 = __floats2half2_rn(f1.z, f1.w);
    ((uint4*)df)[j] = make_uint4(*(uint32_t*)&h0, *(uint32_t*)&h1, *(uint32_t*)&h2, *(uint32_t*)&h3);
}

__global__ void convert_x(const float* __restrict__ x) {
    size_t i = (size_t)blockIdx.x * blockDim.x + threadIdx.x;
    if (i >= X8) return;
    const float4* s = (const float4*)x + i*2;
    split8(s, g_xh, g_xl, i);
    pack_f16(s, g_xf, i);
}
__global__ void convert_cbct() {
    size_t i = (size_t)blockIdx.x * blockDim.x + threadIdx.x;
    if (i >= 2 * C8) return;
    if (i < C8) split8((const float4*)g_ccb + i*2, g_ch, g_cl, i);
    else { size_t j = i - C8; pack_f16((const float4*)g_ct + j*2, g_ctf, j); }
}

// ============================================================
// K5: 3-pass split-bf16 tensor-core argmin (race-free, proven)
// ============================================================
#define RSTRIDE   144
#define SUB_TB    (128 * RSTRIDE)          // 18432
#define OFF_XH    0
#define OFF_XL    SUB_TB
#define OFF_CH    (2 * SUB_TB)
#define OFF_CL    (3 * SUB_TB)
#define STAGE_B3  (4 * SUB_TB)             // 73728
#define OFF_CBN3  (2 * STAGE_B3)           // 147456
#define SM3_DYN   (OFF_CBN3 + KC * 4)      // 151552
#define AM_MARGIN 0.35f

__device__ __forceinline__ void stage_load3(uint32_t dst, int node0, int c0, int kt) {
    int tid = threadIdx.x;
    const __nv_bfloat16* srcs[4] = {
        g_xh + (size_t)node0 * DD, g_xl + (size_t)node0 * DD,
        g_ch + (size_t)c0 * DD,    g_cl + (size_t)c0 * DD };
    #pragma unroll
    for (int s = 0; s < 4; s++) {
        uint32_t d = dst + (uint32_t)s * SUB_TB;
        const __nv_bfloat16* src = srcs[s] + kt * 64;
        #pragma unroll
        for (int it = 0; it < 4; it++) {
            int idx = tid + it * 256;
            int row = idx >> 3, c8 = idx & 7;
            cp_async16(d + (uint32_t)row * RSTRIDE + (uint32_t)c8 * 16,
                       src + (size_t)row * DD + c8 * 8);
        }
    }
}

__global__ __launch_bounds__(256) void argmin_mma3() {
    extern __shared__ char sm[];
    float* scbn = (float*)(sm + OFF_CBN3);
    __shared__ int s_v1;

    int tid = threadIdx.x, lane = tid & 31, wid = tid >> 5;
    int g = lane >> 2, tg = lane & 3;
    int node0 = blockIdx.x * 128;

    int v1 = mma_layout_probe(sm, &s_v1);
    uint32_t offA1 = v1 ? 16u : (uint32_t)(8 * RSTRIDE);
    uint32_t offA2 = v1 ? (uint32_t)(8 * RSTRIDE) : 16u;

    for (int i = tid; i < KC; i += 256) scbn[i] = g_cbn[i];

    uint32_t smb = smem_u32(sm);
    stage_load3(smb, node0, 0, 0);
    CP_COMMIT();

    unsigned long long rs1[2], rs2[2];
    rs1[0] = rs1[1] = rs2[0] = rs2[1] = ~0ULL;

    float acc[16][4];

    for (int t = 0; t < 64; t++) {
        int c = t >> 3, kt = t & 7;
        if (kt == 0) {
            #pragma unroll
            for (int nf = 0; nf < 16; nf++)
                #pragma unroll
                for (int q = 0; q < 4; q++) acc[nf][q] = 0.f;
        }
        if (t < 63) {
            int tn = t + 1;
            stage_load3(smb + (uint32_t)(tn & 1) * STAGE_B3, node0, (tn >> 3) * 128, tn & 7);
            CP_COMMIT();
            CP_WAIT(1);
        } else {
            CP_WAIT(0);
        }
        __syncthreads();

        const char* St = sm + (size_t)(t & 1) * STAGE_B3;
        const char* Axh = St + OFF_XH + (size_t)(wid * 16 + g) * RSTRIDE;
        const char* Axl = St + OFF_XL + (size_t)(wid * 16 + g) * RSTRIDE;
        const char* Bch = St + OFF_CH + (size_t)g * RSTRIDE;
        const char* Bcl = St + OFF_CL + (size_t)g * RSTRIDE;
        #pragma unroll
        for (int ks = 0; ks < 4; ks++) {
            int koff = (ks * 16 + tg * 2) * 2;
            uint32_t h0 = *(const uint32_t*)(Axh + koff);
            uint32_t h1 = *(const uint32_t*)(Axh + koff + offA1);
            uint32_t h2 = *(const uint32_t*)(Axh + koff + offA2);
            uint32_t h3 = *(const uint32_t*)(Axh + koff + 8 * RSTRIDE + 16);
            uint32_t l0 = *(const uint32_t*)(Axl + koff);
            uint32_t l1 = *(const uint32_t*)(Axl + koff + offA1);
            uint32_t l2 = *(const uint32_t*)(Axl + koff + offA2);
            uint32_t l3 = *(const uint32_t*)(Axl + koff + 8 * RSTRIDE + 16);
            int kb = ks * 32 + tg * 4;
            #pragma unroll
            for (int nf = 0; nf < 16; nf++) {
                size_t bro = (size_t)(nf * 8) * RSTRIDE + kb;
                uint32_t bh0 = *(const uint32_t*)(Bch + bro);
                uint32_t bh1 = *(const uint32_t*)(Bch + bro + 16);
                uint32_t bl0 = *(const uint32_t*)(Bcl + bro);
                uint32_t bl1 = *(const uint32_t*)(Bcl + bro + 16);
                mma_bf16(acc[nf], h0, h1, h2, h3, bh0, bh1);
                mma_bf16(acc[nf], h0, h1, h2, h3, bl0, bl1);
                mma_bf16(acc[nf], l0, l1, l2, l3, bh0, bh1);
            }
        }
        __syncthreads();

        if (kt == 7) {
            #pragma unroll
            for (int h = 0; h < 2; h++) {
                unsigned long long s1 = ~0ULL, s2 = ~0ULL;
                #pragma unroll
                for (int nf = 0; nf < 16; nf++) {
                    #pragma unroll
                    for (int q = 0; q < 2; q++) {
                        int code = c * 128 + nf * 8 + tg * 2 + q;
                        float sc = scbn[code] - 2.f * acc[nf][h * 2 + q];
                        unsigned long long p = ((unsigned long long)fkey(sc) << 32) | (uint32_t)code;
                        if (p < s1) { s2 = s1; s1 = p; }
                        else if (p < s2) s2 = p;
                    }
                }
                #pragma unroll
                for (int off = 1; off <= 2; off <<= 1) {
                    unsigned long long o1 = __shfl_xor_sync(~0u, s1, off);
                    unsigned long long o2 = __shfl_xor_sync(~0u, s2, off);
                    if (o1 < s1) { s2 = (s1 < o2) ? s1 : o2; s1 = o1; }
                    else         { s2 = (s2 < o1) ? s2 : o1; }
                }
                if (s1 < rs1[h]) {
                    rs2[h] = (rs1[h] < s2) ? rs1[h] : s2;
                    rs1[h] = s1;
                } else {
                    rs2[h] = (rs2[h] < s1) ? rs2[h] : s1;
                }
            }
        }
    }

    if (tg == 0) {
        #pragma unroll
        for (int h = 0; h < 2; h++) {
            int node = node0 + wid * 16 + h * 8 + g;
            g_idx[node] = (int)(rs1[h] & 0xFFFFFFFFu);
            float f1 = funkey((uint32_t)(rs1[h] >> 32));
            float f2 = funkey((uint32_t)(rs2[h] >> 32));
            if (!(f2 - f1 >= AM_MARGIN)) {
                int p = atomicAdd(&g_nflag, 1);
                g_flag[p] = node;
            }
        }
    }
}

// ============================================================
// K5b: exact fp32 refinement
// ============================================================
__global__ __launch_bounds__(256) void refine3(const float* __restrict__ x) {
    __shared__ __align__(16) float xs[DD];
    __shared__ unsigned long long sbest;
    int tid = threadIdx.x;
    int nf = g_nflag;
    for (int f = blockIdx.x; f < nf; f += gridDim.x) {
        int node = g_flag[f];
        if (tid < 128) ((float4*)xs)[tid] = ((const float4*)x)[(size_t)node * 128 + tid];
        if (tid == 0) sbest = ~0ULL;
        __syncthreads();
        unsigned long long best = ~0ULL;
        #pragma unroll
        for (int cc = 0; cc < 4; cc++) {
            int code = tid + cc * 256;
            const float4* cb = (const float4*)(g_ccb + (size_t)code * DD);
            float dot = 0.f;
            #pragma unroll 8
            for (int q = 0; q < 128; q++) {
                float4 a = ((const float4*)xs)[q], b = cb[q];
                dot += a.x * b.x + a.y * b.y + a.z * b.z + a.w * b.w;
            }
            float sc = g_cbn[code] - 2.f * dot;
            unsigned long long p = ((unsigned long long)fkey(sc) << 32) | (uint32_t)code;
            if (p < best) best = p;
        }
        atomicMin(&sbest, best);
        __syncthreads();
        if (tid == 0) g_idx[node] = (int)(sbest & 0xFFFFFFFFu);
        __syncthreads();
    }
}

// ============================================================
// K6: per node: x copy, z gather, inv norms
// ============================================================
__global__ void node_kernel(const float* __restrict__ x, float* __restrict__ out) {
    int n = blockIdx.x, t = threadIdx.x;
    float4 xv = ((const float4*)x)[(size_t)n*128 + t];
    ((float4*)(out + O_X))[(size_t)n*128 + t] = xv;
    int code = g_idx[n];
    float4 zv = ((const float4*)g_ct)[(size_t)code*128 + t];
    ((float4*)(out + O_Z))[(size_t)n*128 + t] = zv;
    float sx = xv.x*xv.x + xv.y*xv.y + xv.z*xv.z + xv.w*xv.w;
    float sz = zv.x*zv.x + zv.y*zv.y + zv.z*zv.z + zv.w*zv.w;
    #pragma unroll
    for (int off = 16; off; off >>= 1) {
        sx += __shfl_xor_sync(~0u, sx, off);
        sz += __shfl_xor_sync(~0u, sz, off);
    }
    __shared__ float rx[4], rz[4];
    if ((t & 31) == 0) { rx[t >> 5] = sx; rz[t >> 5] = sz; }
    __syncthreads();
    if (t == 0) {
        float nx = sqrtf(rx[0] + rx[1] + rx[2] + rx[3]);
        float nz = sqrtf(rz[0] + rz[1] + rz[2] + rz[3]);
        g_invnx[n] = 1.f / fmaxf(nx, 1e-12f);
        g_invnz[n] = 1.f / fmaxf(nz, 1e-12f);
    }
}

// ============================================================
// K7: pooled means + classifier heads
// ============================================================
__global__ __launch_bounds__(256) void pool_kernel(const float* __restrict__ x,
                                                   const float* __restrict__ clsw,
                                                   const float* __restrict__ clsb,
                                                   float* __restrict__ out) {
    int g = blockIdx.x, t = threadIdx.x;
    __shared__ int idxs[NPG];
    __shared__ float sp[3][DD];
    if (t < NPG) idxs[t] = g_idx[g*NPG + t];
    __syncthreads();
    for (int d = t; d < DD; d += 256) {
        float ax = 0.f, ac = 0.f, ak = 0.f;
        #pragma unroll 4
        for (int nn = 0; nn < NPG; nn++) {
            ax += x[(size_t)(g*NPG + nn)*DD + d];
            int c = idxs[nn];
            ac += g_ccb[(size_t)c*DD + d];
            ak += g_xcb[(size_t)c*DD + d];
        }
        float px = ax * (1.f/128.f);
        float pc = px + ac * (1.f/128.f);
        float pk = ak * (1.f/128.f);
        out[O_PX + (size_t)g*DD + d] = px;
        out[O_PC + (size_t)g*DD + d] = pc;
        sp[0][d] = pc; sp[1][d] = pk; sp[2][d] = px;
    }
    __syncthreads();
    int lane = t & 31, w = t >> 5;
    for (int job = w; job < 30; job += 8) {
        int vec = job / 10, cc = job % 10;
        float a = 0.f;
        for (int d = lane; d < DD; d += 32) a += sp[vec][d] * clsw[(size_t)cc*DD + d];
        #pragma unroll
        for (int off = 16; off; off >>= 1) a += __shfl_xor_sync(~0u, a, off);
        if (lane == 0) {
            long long base = (vec == 0) ? O_CPRE : (vec == 1 ? O_KPRE : O_YPRE);
            out[base + (size_t)g*TCLS + cc] = a + clsb[cc];
        }
    }
}

// ============================================================
// K8: adjacency via SINGLE-PASS fp16 mma (Gram), normalize in epilogue.
// Block = (mode, graph). Warp owns 16 rows x all 128 cols (race-free).
// ============================================================
#define AJ_STAGE  SUB_TB                   // one f16 tile = 18432
#define AJ_DYN    (2 * AJ_STAGE)           // 36864

__device__ __forceinline__ void adj_stage(uint32_t dst, const __half* base, const int* idx_s,
                                          int node0, int mode, int kt) {
    int tid = threadIdx.x;
    #pragma unroll
    for (int it = 0; it < 4; it++) {
        int e = tid + it * 256;              // 0..1023
        int row = e >> 3, c8 = e & 7;
        size_t roff = mode ? (size_t)idx_s[row] : (size_t)(node0 + row);
        cp_async16(dst + (uint32_t)row * RSTRIDE + (uint32_t)c8 * 16,
                   base + roff * DD + kt * 64 + c8 * 8);
    }
}

__global__ __launch_bounds__(256) void adj_mma(float* __restrict__ out) {
    extern __shared__ char sm[];
    __shared__ int s_v1;
    __shared__ int idx_s[NPG];
    __shared__ float invn_s[NPG];

    int tid = threadIdx.x, lane = tid & 31, wid = tid >> 5;
    int g = lane >> 2, tg = lane & 3;
    int b = blockIdx.x;
    int mode = b >> 9;
    int gr = b & 511;
    int node0 = gr * 128;

    int v1 = mma_layout_probe(sm, &s_v1);
    uint32_t offA1 = v1 ? 16u : (uint32_t)(8 * RSTRIDE);
    uint32_t offA2 = v1 ? (uint32_t)(8 * RSTRIDE) : 16u;

    if (tid < NPG) {
        idx_s[tid]  = g_idx[node0 + tid];
        invn_s[tid] = mode ? g_invnz[node0 + tid] : g_invnx[node0 + tid];
    }
    __syncthreads();

    const __half* base = mode ? g_ctf : g_xf;
    uint32_t smb = smem_u32(sm);

    adj_stage(smb, base, idx_s, node0, mode, 0);
    CP_COMMIT();

    float acc[16][4];
    #pragma unroll
    for (int nf = 0; nf < 16; nf++)
        #pragma unroll
        for (int q = 0; q < 4; q++) acc[nf][q] = 0.f;

    for (int kt = 0; kt < 8; kt++) {
        if (kt < 7) {
            adj_stage(smb + (uint32_t)((kt + 1) & 1) * AJ_STAGE, base, idx_s, node0, mode, kt + 1);
            CP_COMMIT();
            CP_WAIT(1);
        } else {
            CP_WAIT(0);
        }
        __syncthreads();

        const char* St = sm + (size_t)(kt & 1) * AJ_STAGE;
        const char* Ah = St + (size_t)(wid * 16 + g) * RSTRIDE;
        #pragma unroll
        for (int ks = 0; ks < 4; ks++) {
            int koff = (ks * 16 + tg * 2) * 2;
            uint32_t a0 = *(const uint32_t*)(Ah + koff);
            uint32_t a1 = *(const uint32_t*)(Ah + koff + offA1);
            uint32_t a2 = *(const uint32_t*)(Ah + koff + offA2);
            uint32_t a3 = *(const uint32_t*)(Ah + koff + 8 * RSTRIDE + 16);
            int kb = ks * 32 + tg * 4;
            #pragma unroll
            for (int nf = 0; nf < 16; nf++) {
                size_t bro = (size_t)(nf * 8 + g) * RSTRIDE + kb;
                uint32_t b0 = *(const uint32_t*)(St + bro);
                uint32_t b1 = *(const uint32_t*)(St + bro + 16);
                mma_f16(acc[nf], a0, a1, a2, a3, b0, b1);
            }
        }
        __syncthreads();
    }

    float* dst = out + (mode ? O_AR : O_AO) + (size_t)gr * (NPG * NPG);
    #pragma unroll
    for (int h = 0; h < 2; h++) {
        int r = wid * 16 + h * 8 + g;
        float invr = invn_s[r];
        #pragma unroll
        for (int nf = 0; nf < 16; nf++) {
            #pragma unroll
            for (int q = 0; q < 2; q++) {
                int c = nf * 8 + tg * 2 + q;
                dst[(size_t)r * NPG + c] = sigm10f(acc[nf][h * 2 + q] * invr * invn_s[c]);
            }
        }
    }
}

// ============================================================
extern "C" void kernel_launch(void* const* d_in, const int* in_sizes, int n_in,
                              void* d_out, int out_size) {
    const float* x      = (const float*)d_in[0];
    const float* cbin   = (const float*)d_in[2];
    const float* fc1w   = (const float*)d_in[3];
    const float* fc1b   = (const float*)d_in[4];
    const float* fc2w   = (const float*)d_in[5];
    const float* fc2b   = (const float*)d_in[6];
    const float* causal = (const float*)d_in[7];
    const float* clsw   = (const float*)d_in[8];
    const float* clsb   = (const float*)d_in[9];
    float* out = (float*)d_out;

    cudaFuncSetAttribute(argmin_mma3, cudaFuncAttributeMaxDynamicSharedMemorySize, SM3_DYN);
    cudaFuncSetAttribute(adj_mma,     cudaFuncAttributeMaxDynamicSharedMemorySize, AJ_DYN);

    // single stream (R10 multi-stream graph regressed; linear schedule is best)
    diag_kernel<<<KC, 256>>>(causal, out);
    mlp_kernel<<<KC, 128>>>(cbin, fc1w, fc1b, fc2w, fc2b);
    gemm_cc<<<dim3(8, 32), 256>>>(causal, 3);           // fused: c1 + causal_cb
    cbn_kernel<<<KC, 128>>>();
    convert_cbct<<<(2 * C8) / 256, 256>>>();
    gemm_cc<<<dim3(8, 16), 256>>>(causal, 2);           // counter_cb
    convert_x<<<X8 / 256, 256>>>(x);
    argmin_mma3<<<NN / 128, 256, SM3_DYN>>>();
    refine3<<<256, 256>>>(x);
    node_kernel<<<NN, 128>>>(x, out);
    pool_kernel<<<GG, 256>>>(x, clsw, clsb, out);
    adj_mma<<<2 * GG, 256, AJ_DYN>>>(out);
}

// round 13
// speedup vs baseline: 1.3136x; 1.0107x over previous
#include <cuda_runtime.h>
#include <cuda_bf16.h>
#include <cuda_fp16.h>
#include <math.h>
#include <stdint.h>

// ---- fixed problem shapes ----
#define GG   512
#define NPG  128
#define NN   65536
#define DD   512
#define KC   1024
#define HHID 128
#define TCLS 10

// ---- device scratch ----
static __device__ float g_ct [KC*DD];
static __device__ float g_cs [KC*DD];
static __device__ float g_c1 [KC*DD];
static __device__ float g_ccb[KC*DD];
static __device__ float g_xcb[KC*DD];
static __device__ float g_cbn[KC];
static __device__ int   g_idx[NN];
static __device__ float g_invnx[NN];
static __device__ float g_invnz[NN];
static __device__ __nv_bfloat16 g_xh[NN*DD];
static __device__ __nv_bfloat16 g_xl[NN*DD];
static __device__ __nv_bfloat16 g_ch[KC*DD];
static __device__ __nv_bfloat16 g_cl[KC*DD];
static __device__ __half g_xf [NN*DD];
static __device__ __half g_ctf[KC*DD];
static __device__ int g_nflag;
static __device__ int g_flag[NN];

// ---- output offsets (floats) ----
#define O_CPRE 0LL
#define O_KPRE 5120LL
#define O_YPRE 10240LL
#define O_AO   15360LL
#define O_AR   8403968LL
#define O_Z    16792576LL
#define O_X    50347008LL
#define O_CD   83901440LL
#define O_CM   84950016LL
#define O_PC   85998592LL
#define O_PX   86260736LL

__device__ __forceinline__ float sigm(float v) { return 1.f / (1.f + expf(-v)); }
__device__ __forceinline__ float sigm10f(float v) { return 1.f / (1.f + __expf(-10.f * v)); }

// ---- portable tensor-core helpers ----
__device__ __forceinline__ uint32_t smem_u32(const void* p) {
    uint32_t a;
    asm("{ .reg .u64 t; cvta.to.shared.u64 t, %1; cvt.u32.u64 %0, t; }" : "=r"(a) : "l"(p));
    return a;
}
__device__ __forceinline__ void mma_bf16(float* d, uint32_t a0, uint32_t a1, uint32_t a2, uint32_t a3,
                                         uint32_t b0, uint32_t b1) {
    asm volatile("mma.sync.aligned.m16n8k16.row.col.f32.bf16.bf16.f32 "
                 "{%0,%1,%2,%3}, {%4,%5,%6,%7}, {%8,%9}, {%0,%1,%2,%3};"
                 : "+f"(d[0]), "+f"(d[1]), "+f"(d[2]), "+f"(d[3])
                 : "r"(a0), "r"(a1), "r"(a2), "r"(a3), "r"(b0), "r"(b1));
}
__device__ __forceinline__ void mma_f16(float* d, uint32_t a0, uint32_t a1, uint32_t a2, uint32_t a3,
                                        uint32_t b0, uint32_t b1) {
    asm volatile("mma.sync.aligned.m16n8k16.row.col.f32.f16.f16.f32 "
                 "{%0,%1,%2,%3}, {%4,%5,%6,%7}, {%8,%9}, {%0,%1,%2,%3};"
                 : "+f"(d[0]), "+f"(d[1]), "+f"(d[2]), "+f"(d[3])
                 : "r"(a0), "r"(a1), "r"(a2), "r"(a3), "r"(b0), "r"(b1));
}
__device__ __forceinline__ void ldmx4(uint32_t a, uint32_t& r0, uint32_t& r1, uint32_t& r2, uint32_t& r3) {
    asm volatile("ldmatrix.sync.aligned.m8n8.x4.shared.b16 {%0,%1,%2,%3}, [%4];"
                 : "=r"(r0), "=r"(r1), "=r"(r2), "=r"(r3) : "r"(a));
}
__device__ __forceinline__ void cp_async16(uint32_t dst, const void* src) {
    asm volatile("cp.async.cg.shared.global [%0], [%1], 16;" :: "r"(dst), "l"(src) : "memory");
}
#define CP_COMMIT()  asm volatile("cp.async.commit_group;" ::: "memory")
#define CP_WAIT(n)   asm volatile("cp.async.wait_group %0;" :: "n"(n) : "memory")

__device__ __forceinline__ uint32_t fkey(float f) {
    uint32_t b = __float_as_uint(f);
    return (b & 0x80000000u) ? ~b : (b | 0x80000000u);
}
__device__ __forceinline__ float funkey(uint32_t k) {
    uint32_t b = (k & 0x80000000u) ? (k & 0x7FFFFFFFu) : ~k;
    return __uint_as_float(b);
}

// Probe: bit0 = A-frag middle registers swapped (v1); bit1 = ldmatrix mapping OK.
// Uses a 16x16 bf16 pattern at stride 144 and checks both the mma fragment
// identity and a ldmatrix.x4 against proven scalar loads.
__device__ __forceinline__ int mma_layout_probe(char* sm, int* s_flag) {
    int tid = threadIdx.x, lane = tid & 31, wid = tid >> 5;
    int g = lane >> 2, tg = lane & 3;
    char* Ap = sm;
    char* Bp = sm + 8192;
    if (tid < 256) {
        int r = tid >> 4, k = tid & 15;
        *(__nv_bfloat16*)(Ap + r * 144 + k * 2) = __float2bfloat16((float)(r * 16 + k));
    }
    if (tid < 128) {
        int n = tid >> 4, k = tid & 15;
        *(__nv_bfloat16*)(Bp + n * 144 + k * 2) = __float2bfloat16((n == 0 && k == 0) ? 1.f : 0.f);
    }
    __syncthreads();
    if (wid == 0) {
        uint32_t a0 = *(uint32_t*)(Ap + g * 144 + tg * 4);
        uint32_t a1 = *(uint32_t*)(Ap + (g + 8) * 144 + tg * 4);
        uint32_t a2 = *(uint32_t*)(Ap + g * 144 + 16 + tg * 4);
        uint32_t a3 = *(uint32_t*)(Ap + (g + 8) * 144 + 16 + tg * 4);
        uint32_t b0 = *(uint32_t*)(Bp + g * 144 + tg * 4);
        uint32_t b1 = *(uint32_t*)(Bp + g * 144 + 16 + tg * 4);
        float d[4] = {0.f, 0.f, 0.f, 0.f};
        mma_bf16(d, a0, a1, a2, a3, b0, b1);
        int bad = (tg == 0) && (d[2] != (float)((g + 8) * 16));
        uint32_t anybad = __ballot_sync(~0u, bad);

        // ldmatrix test: mat0=rows0-7 klo, mat1=rows0-7 khi, mat2=rows8-15 klo, mat3=rows8-15 khi
        uint32_t lane_off = (uint32_t)(((lane >> 4) * 8 + (lane & 7)) * 144 + ((lane >> 3) & 1) * 16);
        uint32_t r0, r1, r2, r3;
        ldmx4(smem_u32(Ap) + lane_off, r0, r1, r2, r3);
        int bad2 = (r0 != a0) | (r1 != a2) | (r2 != a1) | (r3 != a3);
        // expected: r0 = rows0-7 klo  = A[g][2tg..]      = a0
        //           r1 = rows0-7 khi  = A[g][2tg+8..]    = a2
        //           r2 = rows8-15 klo = A[g+8][2tg..]    = a1
        //           r3 = rows8-15 khi = A[g+8][2tg+8..]  = a3
        uint32_t anybad2 = __ballot_sync(~0u, bad2);
        if (lane == 0) *s_flag = ((anybad != 0) ? 1 : 0) | ((anybad2 == 0) ? 2 : 0);
    }
    __syncthreads();
    int v = *s_flag;
    __syncthreads();
    return v;
}

// ============================================================
// K1: codebook MLP
// ============================================================
__global__ void mlp_kernel(const float* __restrict__ cbin,
                           const float* __restrict__ fc1w, const float* __restrict__ fc1b,
                           const float* __restrict__ fc2w, const float* __restrict__ fc2b) {
    __shared__ float row[DD];
    __shared__ float hs[HHID];
    int k = blockIdx.x, t = threadIdx.x;
    for (int d = t; d < DD; d += 128) row[d] = cbin[(size_t)k*DD + d];
    __syncthreads();
    float acc = fc1b[t];
    const float* w = fc1w + (size_t)t*DD;
    #pragma unroll 8
    for (int d = 0; d < DD; d++) acc += row[d] * w[d];
    hs[t] = sigm(acc);
    __syncthreads();
    for (int d = t; d < DD; d += 128) {
        float a = fc2b[d];
        const float* w2 = fc2w + (size_t)d*HHID;
        #pragma unroll 8
        for (int h = 0; h < HHID; h++) a += hs[h] * w2[h];
        g_ct[(size_t)k*DD + d] = a;
        g_cs[(size_t)k*DD + d] = sigm(a);
    }
}

// ============================================================
// K2: diag / off-diag outputs
// ============================================================
__global__ void diag_kernel(const float* __restrict__ causal, float* __restrict__ out) {
    int i = blockIdx.x;
    size_t base = (size_t)i * KC;
    for (int j = threadIdx.x; j < KC; j += blockDim.x) {
        float c = causal[base + j];
        bool dg = (j == i);
        out[O_CD + base + j] = dg ? c : 0.f;
        out[O_CM + base + j] = dg ? 0.f : c;
    }
}

// ============================================================
// K3: codebook GEMMs; mode 3 = fused modes 0+1 in one grid (8,32)
// ============================================================
__global__ __launch_bounds__(256) void gemm_cc(const float* __restrict__ A, int mode) {
    int by = blockIdx.y;
    if (mode == 3) { mode = (by < 16) ? 0 : 1; by &= 15; }
    const float* B = (mode == 2) ? g_c1 : g_cs;
    float* C = (mode == 0) ? g_c1 : (mode == 1 ? g_ccb : g_xcb);
    float diag_patch = (mode == 0) ? 0.f : 1.f;
    bool scale = (mode == 1);

    __shared__ __align__(16) float As[16][68];
    __shared__ __align__(16) float Bs[16][68];
    int tid = threadIdx.x, tx = tid & 15, ty = tid >> 4;
    int bm = by * 64, bn = blockIdx.x * 64;
    float acc[4][4] = {};
    for (int k0 = 0; k0 < KC; k0 += 16) {
        #pragma unroll
        for (int p = 0; p < 4; p++) {
            int e = tid + p * 256;
            int r = e >> 4, kk = e & 15;
            int grow = bm + r, gk = k0 + kk;
            As[kk][r] = (grow == gk) ? diag_patch : A[(size_t)grow*KC + gk];
        }
        #pragma unroll
        for (int p = 0; p < 4; p++) {
            int e = tid + p * 256;
            int kk = e >> 6, c = e & 63;
            int gk = k0 + kk;
            float bv = B[(size_t)gk*DD + bn + c];
            if (scale) bv *= A[(size_t)gk*KC + gk];
            Bs[kk][c] = bv;
        }
        __syncthreads();
        #pragma unroll
        for (int kk = 0; kk < 16; kk++) {
            float4 a = *(const float4*)&As[kk][ty*4];
            float4 b = *(const float4*)&Bs[kk][tx*4];
            float av[4] = {a.x, a.y, a.z, a.w};
            float bv[4] = {b.x, b.y, b.z, b.w};
            #pragma unroll
            for (int i = 0; i < 4; i++)
                #pragma unroll
                for (int j = 0; j < 4; j++)
                    acc[i][j] += av[i] * bv[j];
        }
        __syncthreads();
    }
    #pragma unroll
    for (int i = 0; i < 4; i++) {
        float4 v = make_float4(acc[i][0], acc[i][1], acc[i][2], acc[i][3]);
        *(float4*)&C[(size_t)(bm + ty*4 + i)*DD + bn + tx*4] = v;
    }
}

// ============================================================
// K4: g_cbn + reset flag counter
// ============================================================
__global__ void cbn_kernel() {
    if (blockIdx.x == 0 && threadIdx.x == 0) g_nflag = 0;
    int k = blockIdx.x;
    float s = 0.f;
    for (int d = threadIdx.x; d < DD; d += 128) {
        float v = g_ccb[(size_t)k*DD + d];
        s += v * v;
    }
    #pragma unroll
    for (int off = 16; off; off >>= 1) s += __shfl_xor_sync(~0u, s, off);
    __shared__ float red[4];
    if ((threadIdx.x & 31) == 0) red[threadIdx.x >> 5] = s;
    __syncthreads();
    if (threadIdx.x == 0) g_cbn[k] = red[0] + red[1] + red[2] + red[3];
}

// ============================================================
// K4b: conversions
// ============================================================
#define X8   (NN*DD/8)
#define C8   (KC*DD/8)

__device__ __forceinline__ void split8(const float4* s, __nv_bfloat16* dh, __nv_bfloat16* dl, size_t j) {
    float4 f0 = s[0], f1 = s[1];
    float f[8] = {f0.x, f0.y, f0.z, f0.w, f1.x, f1.y, f1.z, f1.w};
    unsigned short hb[8], lb[8];
    #pragma unroll
    for (int e = 0; e < 8; e++) {
        __nv_bfloat16 h = __float2bfloat16(f[e]);
        float r = f[e] - __bfloat162float(h);
        __nv_bfloat16 l = __float2bfloat16(r);
        hb[e] = __nv_bfloat16_raw(h).x;
        lb[e] = __nv_bfloat16_raw(l).x;
    }
    ((uint4*)dh)[j] = make_uint4(hb[0]|(hb[1]<<16), hb[2]|(hb[3]<<16), hb[4]|(hb[5]<<16), hb[6]|(hb[7]<<16));
    ((uint4*)dl)[j] = make_uint4(lb[0]|(lb[1]<<16), lb[2]|(lb[3]<<16), lb[4]|(lb[5]<<16), lb[6]|(lb[7]<<16));
}
__device__ __forceinline__ void pack_f16(const float4* s, __half* df, size_t j) {
    float4 f0 = s[0], f1 = s[1];
    __half2 h0 = __floats2half2_rn(f0.x, f0.y);
    __half2 h1 = __floats2half2_rn(f0.z, f0.w);
    __half2 h2 = __floats2half2_rn(f1.x, f1.y);
    __half2 h3 = __floats2half2_rn(f1.z, f1.w);
    ((uint4*)df)[j] = make_uint4(*(uint32_t*)&h0, *(uint32_t*)&h1, *(uint32_t*)&h2, *(uint32_t*)&h3);
}

__global__ void convert_x(const float* __restrict__ x) {
    size_t i = (size_t)blockIdx.x * blockDim.x + threadIdx.x;
    if (i >= X8) return;
    const float4* s = (const float4*)x + i*2;
    split8(s, g_xh, g_xl, i);
    pack_f16(s, g_xf, i);
}
__global__ void convert_cbct() {
    size_t i = (size_t)blockIdx.x * blockDim.x + threadIdx.x;
    if (i >= 2 * C8) return;
    if (i < C8) split8((const float4*)g_ccb + i*2, g_ch, g_cl, i);
    else { size_t j = i - C8; pack_f16((const float4*)g_ct + j*2, g_ctf, j); }
}

// ============================================================
// K5: 3-pass split-bf16 tensor-core argmin; B fragments via ldmatrix.x4
// when probe-verified, else proven scalar LDS path.
// ============================================================
#define RSTRIDE   144
#define SUB_TB    (128 * RSTRIDE)
#define OFF_XH    0
#define OFF_XL    SUB_TB
#define OFF_CH    (2 * SUB_TB)
#define OFF_CL    (3 * SUB_TB)
#define STAGE_B3  (4 * SUB_TB)
#define OFF_CBN3  (2 * STAGE_B3)
#define SM3_DYN   (OFF_CBN3 + KC * 4)
#define AM_MARGIN 0.35f

__device__ __forceinline__ void stage_load3(uint32_t dst, int node0, int c0, int kt) {
    int tid = threadIdx.x;
    const __nv_bfloat16* srcs[4] = {
        g_xh + (size_t)node0 * DD, g_xl + (size_t)node0 * DD,
        g_ch + (size_t)c0 * DD,    g_cl + (size_t)c0 * DD };
    #pragma unroll
    for (int s = 0; s < 4; s++) {
        uint32_t d = dst + (uint32_t)s * SUB_TB;
        const __nv_bfloat16* src = srcs[s] + kt * 64;
        #pragma unroll
        for (int it = 0; it < 4; it++) {
            int idx = tid + it * 256;
            int row = idx >> 3, c8 = idx & 7;
            cp_async16(d + (uint32_t)row * RSTRIDE + (uint32_t)c8 * 16,
                       src + (size_t)row * DD + c8 * 8);
        }
    }
}

__global__ __launch_bounds__(256) void argmin_mma3() {
    extern __shared__ char sm[];
    float* scbn = (float*)(sm + OFF_CBN3);
    __shared__ int s_v1;

    int tid = threadIdx.x, lane = tid & 31, wid = tid >> 5;
    int g = lane >> 2, tg = lane & 3;
    int node0 = blockIdx.x * 128;

    int flags = mma_layout_probe(sm, &s_v1);
    int v1 = flags & 1;
    int use_ldm = (flags >> 1) & 1;
    uint32_t offA1 = v1 ? 16u : (uint32_t)(8 * RSTRIDE);
    uint32_t offA2 = v1 ? (uint32_t)(8 * RSTRIDE) : 16u;
    uint32_t lane_off = (uint32_t)(((lane >> 4) * 8 + (lane & 7)) * 144 + ((lane >> 3) & 1) * 16);

    for (int i = tid; i < KC; i += 256) scbn[i] = g_cbn[i];

    uint32_t smb = smem_u32(sm);
    stage_load3(smb, node0, 0, 0);
    CP_COMMIT();

    unsigned long long rs1[2], rs2[2];
    rs1[0] = rs1[1] = rs2[0] = rs2[1] = ~0ULL;

    float acc[16][4];

    for (int t = 0; t < 64; t++) {
        int c = t >> 3, kt = t & 7;
        if (kt == 0) {
            #pragma unroll
            for (int nf = 0; nf < 16; nf++)
                #pragma unroll
                for (int q = 0; q < 4; q++) acc[nf][q] = 0.f;
        }
        if (t < 63) {
            int tn = t + 1;
            stage_load3(smb + (uint32_t)(tn & 1) * STAGE_B3, node0, (tn >> 3) * 128, tn & 7);
            CP_COMMIT();
            CP_WAIT(1);
        } else {
            CP_WAIT(0);
        }
        __syncthreads();

        uint32_t StU = smb + (uint32_t)(t & 1) * STAGE_B3;
        const char* St = sm + (size_t)(t & 1) * STAGE_B3;
        const char* Axh = St + OFF_XH + (size_t)(wid * 16 + g) * RSTRIDE;
        const char* Axl = St + OFF_XL + (size_t)(wid * 16 + g) * RSTRIDE;

        if (use_ldm) {
            uint32_t BchU = StU + OFF_CH;
            uint32_t BclU = StU + OFF_CL;
            #pragma unroll
            for (int ks = 0; ks < 4; ks++) {
                int koff = (ks * 16 + tg * 2) * 2;
                uint32_t h0 = *(const uint32_t*)(Axh + koff);
                uint32_t h1 = *(const uint32_t*)(Axh + koff + offA1);
                uint32_t h2 = *(const uint32_t*)(Axh + koff + offA2);
                uint32_t h3 = *(const uint32_t*)(Axh + koff + 8 * RSTRIDE + 16);
                uint32_t l0 = *(const uint32_t*)(Axl + koff);
                uint32_t l1 = *(const uint32_t*)(Axl + koff + offA1);
                uint32_t l2 = *(const uint32_t*)(Axl + koff + offA2);
                uint32_t l3 = *(const uint32_t*)(Axl + koff + 8 * RSTRIDE + 16);
                uint32_t kso = (uint32_t)ks * 32 + lane_off;
                uint32_t b[8][2];
                // bh for nf 0..7: hh + lh passes
                #pragma unroll
                for (int j = 0; j < 4; j++)
                    ldmx4(BchU + (uint32_t)j * 2304 + kso, b[2*j][0], b[2*j][1], b[2*j+1][0], b[2*j+1][1]);
                #pragma unroll
                for (int nf = 0; nf < 8; nf++) {
                    mma_bf16(acc[nf], h0, h1, h2, h3, b[nf][0], b[nf][1]);
                    mma_bf16(acc[nf], l0, l1, l2, l3, b[nf][0], b[nf][1]);
                }
                // bh for nf 8..15
                #pragma unroll
                for (int j = 0; j < 4; j++)
                    ldmx4(BchU + (uint32_t)(j + 4) * 2304 + kso, b[2*j][0], b[2*j][1], b[2*j+1][0], b[2*j+1][1]);
                #pragma unroll
                for (int nf = 0; nf < 8; nf++) {
                    mma_bf16(acc[8 + nf], h0, h1, h2, h3, b[nf][0], b[nf][1]);
                    mma_bf16(acc[8 + nf], l0, l1, l2, l3, b[nf][0], b[nf][1]);
                }
                // bl for nf 0..7: hl pass
                #pragma unroll
                for (int j = 0; j < 4; j++)
                    ldmx4(BclU + (uint32_t)j * 2304 + kso, b[2*j][0], b[2*j][1], b[2*j+1][0], b[2*j+1][1]);
                #pragma unroll
                for (int nf = 0; nf < 8; nf++)
                    mma_bf16(acc[nf], h0, h1, h2, h3, b[nf][0], b[nf][1]);
                // bl for nf 8..15
                #pragma unroll
                for (int j = 0; j < 4; j++)
                    ldmx4(BclU + (uint32_t)(j + 4) * 2304 + kso, b[2*j][0], b[2*j][1], b[2*j+1][0], b[2*j+1][1]);
                #pragma unroll
                for (int nf = 0; nf < 8; nf++)
                    mma_bf16(acc[8 + nf], h0, h1, h2, h3, b[nf][0], b[nf][1]);
            }
        } else {
            const char* Bch = St + OFF_CH + (size_t)g * RSTRIDE;
            const char* Bcl = St + OFF_CL + (size_t)g * RSTRIDE;
            #pragma unroll
            for (int ks = 0; ks < 4; ks++) {
                int koff = (ks * 16 + tg * 2) * 2;
                uint32_t h0 = *(const uint32_t*)(Axh + koff);
                uint32_t h1 = *(const uint32_t*)(Axh + koff + offA1);
                uint32_t h2 = *(const uint32_t*)(Axh + koff + offA2);
                uint32_t h3 = *(const uint32_t*)(Axh + koff + 8 * RSTRIDE + 16);
                uint32_t l0 = *(const uint32_t*)(Axl + koff);
                uint32_t l1 = *(const uint32_t*)(Axl + koff + offA1);
                uint32_t l2 = *(const uint32_t*)(Axl + koff + offA2);
                uint32_t l3 = *(const uint32_t*)(Axl + koff + 8 * RSTRIDE + 16);
                int kb = ks * 32 + tg * 4;
                #pragma unroll
                for (int nf = 0; nf < 16; nf++) {
                    size_t bro = (size_t)(nf * 8) * RSTRIDE + kb;
                    uint32_t bh0 = *(const uint32_t*)(Bch + bro);
                    uint32_t bh1 = *(const uint32_t*)(Bch + bro + 16);
                    uint32_t bl0 = *(const uint32_t*)(Bcl + bro);
                    uint32_t bl1 = *(const uint32_t*)(Bcl + bro + 16);
                    mma_bf16(acc[nf], h0, h1, h2, h3, bh0, bh1);
                    mma_bf16(acc[nf], h0, h1, h2, h3, bl0, bl1);
                    mma_bf16(acc[nf], l0, l1, l2, l3, bh0, bh1);
                }
            }
        }
        __syncthreads();

        if (kt == 7) {
            #pragma unroll
            for (int h = 0; h < 2; h++) {
                unsigned long long s1 = ~0ULL, s2 = ~0ULL;
                #pragma unroll
                for (int nf = 0; nf < 16; nf++) {
                    #pragma unroll
                    for (int q = 0; q < 2; q++) {
                        int code = c * 128 + nf * 8 + tg * 2 + q;
                        float sc = scbn[code] - 2.f * acc[nf][h * 2 + q];
                        unsigned long long p = ((unsigned long long)fkey(sc) << 32) | (uint32_t)code;
                        if (p < s1) { s2 = s1; s1 = p; }
                        else if (p < s2) s2 = p;
                    }
                }
                #pragma unroll
                for (int off = 1; off <= 2; off <<= 1) {
                    unsigned long long o1 = __shfl_xor_sync(~0u, s1, off);
                    unsigned long long o2 = __shfl_xor_sync(~0u, s2, off);
                    if (o1 < s1) { s2 = (s1 < o2) ? s1 : o2; s1 = o1; }
                    else         { s2 = (s2 < o1) ? s2 : o1; }
                }
                if (s1 < rs1[h]) {
                    rs2[h] = (rs1[h] < s2) ? rs1[h] : s2;
                    rs1[h] = s1;
                } else {
                    rs2[h] = (rs2[h] < s1) ? rs2[h] : s1;
                }
            }
        }
    }

    if (tg == 0) {
        #pragma unroll
        for (int h = 0; h < 2; h++) {
            int node = node0 + wid * 16 + h * 8 + g;
            g_idx[node] = (int)(rs1[h] & 0xFFFFFFFFu);
            float f1 = funkey((uint32_t)(rs1[h] >> 32));
            float f2 = funkey((uint32_t)(rs2[h] >> 32));
            if (!(f2 - f1 >= AM_MARGIN)) {
                int p = atomicAdd(&g_nflag, 1);
                g_flag[p] = node;
            }
        }
    }
}

// ============================================================
// K5b: exact fp32 refinement
// ============================================================
__global__ __launch_bounds__(256) void refine3(const float* __restrict__ x) {
    __shared__ __align__(16) float xs[DD];
    __shared__ unsigned long long sbest;
    int tid = threadIdx.x;
    int nf = g_nflag;
    for (int f = blockIdx.x; f < nf; f += gridDim.x) {
        int node = g_flag[f];
        if (tid < 128) ((float4*)xs)[tid] = ((const float4*)x)[(size_t)node * 128 + tid];
        if (tid == 0) sbest = ~0ULL;
        __syncthreads();
        unsigned long long best = ~0ULL;
        #pragma unroll
        for (int cc = 0; cc < 4; cc++) {
            int code = tid + cc * 256;
            const float4* cb = (const float4*)(g_ccb + (size_t)code * DD);
            float dot = 0.f;
            #pragma unroll 8
            for (int q = 0; q < 128; q++) {
                float4 a = ((const float4*)xs)[q], b = cb[q];
                dot += a.x * b.x + a.y * b.y + a.z * b.z + a.w * b.w;
            }
            float sc = g_cbn[code] - 2.f * dot;
            unsigned long long p = ((unsigned long long)fkey(sc) << 32) | (uint32_t)code;
            if (p < best) best = p;
        }
        atomicMin(&sbest, best);
        __syncthreads();
        if (tid == 0) g_idx[node] = (int)(sbest & 0xFFFFFFFFu);
        __syncthreads();
    }
}

// ============================================================
// K6: per node: x copy, z gather, inv norms
// ============================================================
__global__ void node_kernel(const float* __restrict__ x, float* __restrict__ out) {
    int n = blockIdx.x, t = threadIdx.x;
    float4 xv = ((const float4*)x)[(size_t)n*128 + t];
    ((float4*)(out + O_X))[(size_t)n*128 + t] = xv;
    int code = g_idx[n];
    float4 zv = ((const float4*)g_ct)[(size_t)code*128 + t];
    ((float4*)(out + O_Z))[(size_t)n*128 + t] = zv;
    float sx = xv.x*xv.x + xv.y*xv.y + xv.z*xv.z + xv.w*xv.w;
    float sz = zv.x*zv.x + zv.y*zv.y + zv.z*zv.z + zv.w*zv.w;
    #pragma unroll
    for (int off = 16; off; off >>= 1) {
        sx += __shfl_xor_sync(~0u, sx, off);
        sz += __shfl_xor_sync(~0u, sz, off);
    }
    __shared__ float rx[4], rz[4];
    if ((t & 31) == 0) { rx[t >> 5] = sx; rz[t >> 5] = sz; }
    __syncthreads();
    if (t == 0) {
        float nx = sqrtf(rx[0] + rx[1] + rx[2] + rx[3]);
        float nz = sqrtf(rz[0] + rz[1] + rz[2] + rz[3]);
        g_invnx[n] = 1.f / fmaxf(nx, 1e-12f);
        g_invnz[n] = 1.f / fmaxf(nz, 1e-12f);
    }
}

// ============================================================
// K7: pooled means + classifier heads
// ============================================================
__global__ __launch_bounds__(256) void pool_kernel(const float* __restrict__ x,
                                                   const float* __restrict__ clsw,
                                                   const float* __restrict__ clsb,
                                                   float* __restrict__ out) {
    int g = blockIdx.x, t = threadIdx.x;
    __shared__ int idxs[NPG];
    __shared__ float sp[3][DD];
    if (t < NPG) idxs[t] = g_idx[g*NPG + t];
    __syncthreads();
    for (int d = t; d < DD; d += 256) {
        float ax = 0.f, ac = 0.f, ak = 0.f;
        #pragma unroll 4
        for (int nn = 0; nn < NPG; nn++) {
            ax += x[(size_t)(g*NPG + nn)*DD + d];
            int c = idxs[nn];
            ac += g_ccb[(size_t)c*DD + d];
            ak += g_xcb[(size_t)c*DD + d];
        }
        float px = ax * (1.f/128.f);
        float pc = px + ac * (1.f/128.f);
        float pk = ak * (1.f/128.f);
        out[O_PX + (size_t)g*DD + d] = px;
        out[O_PC + (size_t)g*DD + d] = pc;
        sp[0][d] = pc; sp[1][d] = pk; sp[2][d] = px;
    }
    __syncthreads();
    int lane = t & 31, w = t >> 5;
    for (int job = w; job < 30; job += 8) {
        int vec = job / 10, cc = job % 10;
        float a = 0.f;
        for (int d = lane; d < DD; d += 32) a += sp[vec][d] * clsw[(size_t)cc*DD + d];
        #pragma unroll
        for (int off = 16; off; off >>= 1) a += __shfl_xor_sync(~0u, a, off);
        if (lane == 0) {
            long long base = (vec == 0) ? O_CPRE : (vec == 1 ? O_KPRE : O_YPRE);
            out[base + (size_t)g*TCLS + cc] = a + clsb[cc];
        }
    }
}

// ============================================================
// K8: adjacency via single-pass fp16 mma (Gram), normalize in epilogue.
// ============================================================
#define AJ_STAGE  SUB_TB
#define AJ_DYN    (2 * AJ_STAGE)

__device__ __forceinline__ void adj_stage(uint32_t dst, const __half* base, const int* idx_s,
                                          int node0, int mode, int kt) {
    int tid = threadIdx.x;
    #pragma unroll
    for (int it = 0; it < 4; it++) {
        int e = tid + it * 256;
        int row = e >> 3, c8 = e & 7;
        size_t roff = mode ? (size_t)idx_s[row] : (size_t)(node0 + row);
        cp_async16(dst + (uint32_t)row * RSTRIDE + (uint32_t)c8 * 16,
                   base + roff * DD + kt * 64 + c8 * 8);
    }
}

__global__ __launch_bounds__(256) void adj_mma(float* __restrict__ out) {
    extern __shared__ char sm[];
    __shared__ int s_v1;
    __shared__ int idx_s[NPG];
    __shared__ float invn_s[NPG];

    int tid = threadIdx.x, lane = tid & 31, wid = tid >> 5;
    int g = lane >> 2, tg = lane & 3;
    int b = blockIdx.x;
    int mode = b >> 9;
    int gr = b & 511;
    int node0 = gr * 128;

    int flags = mma_layout_probe(sm, &s_v1);
    int v1 = flags & 1;
    uint32_t offA1 = v1 ? 16u : (uint32_t)(8 * RSTRIDE);
    uint32_t offA2 = v1 ? (uint32_t)(8 * RSTRIDE) : 16u;

    if (tid < NPG) {
        idx_s[tid]  = g_idx[node0 + tid];
        invn_s[tid] = mode ? g_invnz[node0 + tid] : g_invnx[node0 + tid];
    }
    __syncthreads();

    const __half* base = mode ? g_ctf : g_xf;
    uint32_t smb = smem_u32(sm);

    adj_stage(smb, base, idx_s, node0, mode, 0);
    CP_COMMIT();

    float acc[16][4];
    #pragma unroll
    for (int nf = 0; nf < 16; nf++)
        #pragma unroll
        for (int q = 0; q < 4; q++) acc[nf][q] = 0.f;

    for (int kt = 0; kt < 8; kt++) {
        if (kt < 7) {
            adj_stage(smb + (uint32_t)((kt + 1) & 1) * AJ_STAGE, base, idx_s, node0, mode, kt + 1);
            CP_COMMIT();
            CP_WAIT(1);
        } else {
            CP_WAIT(0);
        }
        __syncthreads();

        const char* St = sm + (size_t)(kt & 1) * AJ_STAGE;
        const char* Ah = St + (size_t)(wid * 16 + g) * RSTRIDE;
        #pragma unroll
        for (int ks = 0; ks < 4; ks++) {
            int koff = (ks * 16 + tg * 2) * 2;
            uint32_t a0 = *(const uint32_t*)(Ah + koff);
            uint32_t a1 = *(const uint32_t*)(Ah + koff + offA1);
            uint32_t a2 = *(const uint32_t*)(Ah + koff + offA2);
            uint32_t a3 = *(const uint32_t*)(Ah + koff + 8 * RSTRIDE + 16);
            int kb = ks * 32 + tg * 4;
            #pragma unroll
            for (int nf = 0; nf < 16; nf++) {
                size_t bro = (size_t)(nf * 8 + g) * RSTRIDE + kb;
                uint32_t b0 = *(const uint32_t*)(St + bro);
                uint32_t b1 = *(const uint32_t*)(St + bro + 16);
                mma_f16(acc[nf], a0, a1, a2, a3, b0, b1);
            }
        }
        __syncthreads();
    }

    float* dst = out + (mode ? O_AR : O_AO) + (size_t)gr * (NPG * NPG);
    #pragma unroll
    for (int h = 0; h < 2; h++) {
        int r = wid * 16 + h * 8 + g;
        float invr = invn_s[r];
        #pragma unroll
        for (int nf = 0; nf < 16; nf++) {
            #pragma unroll
            for (int q = 0; q < 2; q++) {
                int c = nf * 8 + tg * 2 + q;
                dst[(size_t)r * NPG + c] = sigm10f(acc[nf][h * 2 + q] * invr * invn_s[c]);
            }
        }
    }
}

// ============================================================
extern "C" void kernel_launch(void* const* d_in, const int* in_sizes, int n_in,
                              void* d_out, int out_size) {
    const float* x      = (const float*)d_in[0];
    const float* cbin   = (const float*)d_in[2];
    const float* fc1w   = (const float*)d_in[3];
    const float* fc1b   = (const float*)d_in[4];
    const float* fc2w   = (const float*)d_in[5];
    const float* fc2b   = (const float*)d_in[6];
    const float* causal = (const float*)d_in[7];
    const float* clsw   = (const float*)d_in[8];
    const float* clsb   = (const float*)d_in[9];
    float* out = (float*)d_out;

    cudaFuncSetAttribute(argmin_mma3, cudaFuncAttributeMaxDynamicSharedMemorySize, SM3_DYN);
    cudaFuncSetAttribute(adj_mma,     cudaFuncAttributeMaxDynamicSharedMemorySize, AJ_DYN);

    diag_kernel<<<KC, 256>>>(causal, out);
    mlp_kernel<<<KC, 128>>>(cbin, fc1w, fc1b, fc2w, fc2b);
    gemm_cc<<<dim3(8, 32), 256>>>(causal, 3);           // fused: c1 + causal_cb
    cbn_kernel<<<KC, 128>>>();
    convert_cbct<<<(2 * C8) / 256, 256>>>();
    gemm_cc<<<dim3(8, 16), 256>>>(causal, 2);           // counter_cb
    convert_x<<<X8 / 256, 256>>>(x);
    argmin_mma3<<<NN / 128, 256, SM3_DYN>>>();
    refine3<<<256, 256>>>(x);
    node_kernel<<<NN, 128>>>(x, out);
    pool_kernel<<<GG, 256>>>(x, clsw, clsb, out);
    adj_mma<<<2 * GG, 256, AJ_DYN>>>(out);
}

// round 14
// speedup vs baseline: 1.3380x; 1.0185x over previous
#include <cuda_runtime.h>
#include <cuda_bf16.h>
#include <cuda_fp16.h>
#include <math.h>
#include <stdint.h>

// ---- fixed problem shapes ----
#define GG   512
#define NPG  128
#define NN   65536
#define DD   512
#define KC   1024
#define HHID 128
#define TCLS 10

// ---- device scratch ----
static __device__ float g_ct [KC*DD];
static __device__ float g_cs [KC*DD];
static __device__ float g_c1 [KC*DD];
static __device__ float g_ccb[KC*DD];
static __device__ float g_xcb[KC*DD];
static __device__ float g_cbn[KC];
static __device__ int   g_idx[NN];
static __device__ float g_invnx[NN];
static __device__ float g_invnz[NN];
static __device__ __nv_bfloat16 g_xh[NN*DD];
static __device__ __nv_bfloat16 g_xl[NN*DD];
static __device__ __nv_bfloat16 g_ch[KC*DD];
static __device__ __nv_bfloat16 g_cl[KC*DD];
static __device__ __half g_xf [NN*DD];
static __device__ __half g_ctf[KC*DD];
static __device__ int g_nflagA;          // pairwise refine queue
static __device__ int g_flagA[NN];
static __device__ int g_flagAC[NN];      // c1 | (c2<<16)
static __device__ int g_nflagB;          // full-scan refine queue (3-way clusters)
static __device__ int g_flagB[NN];

// ---- output offsets (floats) ----
#define O_CPRE 0LL
#define O_KPRE 5120LL
#define O_YPRE 10240LL
#define O_AO   15360LL
#define O_AR   8403968LL
#define O_Z    16792576LL
#define O_X    50347008LL
#define O_CD   83901440LL
#define O_CM   84950016LL
#define O_PC   85998592LL
#define O_PX   86260736LL

__device__ __forceinline__ float sigm(float v) { return 1.f / (1.f + expf(-v)); }
__device__ __forceinline__ float sigm10f(float v) { return 1.f / (1.f + __expf(-10.f * v)); }

// ---- portable tensor-core helpers ----
__device__ __forceinline__ uint32_t smem_u32(const void* p) {
    uint32_t a;
    asm("{ .reg .u64 t; cvta.to.shared.u64 t, %1; cvt.u32.u64 %0, t; }" : "=r"(a) : "l"(p));
    return a;
}
__device__ __forceinline__ void mma_bf16(float* d, uint32_t a0, uint32_t a1, uint32_t a2, uint32_t a3,
                                         uint32_t b0, uint32_t b1) {
    asm volatile("mma.sync.aligned.m16n8k16.row.col.f32.bf16.bf16.f32 "
                 "{%0,%1,%2,%3}, {%4,%5,%6,%7}, {%8,%9}, {%0,%1,%2,%3};"
                 : "+f"(d[0]), "+f"(d[1]), "+f"(d[2]), "+f"(d[3])
                 : "r"(a0), "r"(a1), "r"(a2), "r"(a3), "r"(b0), "r"(b1));
}
__device__ __forceinline__ void mma_f16(float* d, uint32_t a0, uint32_t a1, uint32_t a2, uint32_t a3,
                                        uint32_t b0, uint32_t b1) {
    asm volatile("mma.sync.aligned.m16n8k16.row.col.f32.f16.f16.f32 "
                 "{%0,%1,%2,%3}, {%4,%5,%6,%7}, {%8,%9}, {%0,%1,%2,%3};"
                 : "+f"(d[0]), "+f"(d[1]), "+f"(d[2]), "+f"(d[3])
                 : "r"(a0), "r"(a1), "r"(a2), "r"(a3), "r"(b0), "r"(b1));
}
__device__ __forceinline__ void ldmx4(uint32_t a, uint32_t& r0, uint32_t& r1, uint32_t& r2, uint32_t& r3) {
    asm volatile("ldmatrix.sync.aligned.m8n8.x4.shared.b16 {%0,%1,%2,%3}, [%4];"
                 : "=r"(r0), "=r"(r1), "=r"(r2), "=r"(r3) : "r"(a));
}
__device__ __forceinline__ void cp_async16(uint32_t dst, const void* src) {
    asm volatile("cp.async.cg.shared.global [%0], [%1], 16;" :: "r"(dst), "l"(src) : "memory");
}
#define CP_COMMIT()  asm volatile("cp.async.commit_group;" ::: "memory")
#define CP_WAIT(n)   asm volatile("cp.async.wait_group %0;" :: "n"(n) : "memory")

__device__ __forceinline__ uint32_t fkey(float f) {
    uint32_t b = __float_as_uint(f);
    return (b & 0x80000000u) ? ~b : (b | 0x80000000u);
}
__device__ __forceinline__ float funkey(uint32_t k) {
    uint32_t b = (k & 0x80000000u) ? (k & 0x7FFFFFFFu) : ~k;
    return __uint_as_float(b);
}
// insert v into sorted triple (s1<=s2<=s3), keeping 3 smallest
__device__ __forceinline__ void ins3(unsigned long long& s1, unsigned long long& s2,
                                     unsigned long long& s3, unsigned long long v) {
    if (v < s1)      { s3 = s2; s2 = s1; s1 = v; }
    else if (v < s2) { s3 = s2; s2 = v; }
    else if (v < s3) { s3 = v; }
}

// Probe: bit0 = A-frag middle registers swapped (v1); bit1 = ldmatrix mapping OK.
__device__ __forceinline__ int mma_layout_probe(char* sm, int* s_flag) {
    int tid = threadIdx.x, lane = tid & 31, wid = tid >> 5;
    int g = lane >> 2, tg = lane & 3;
    char* Ap = sm;
    char* Bp = sm + 8192;
    if (tid < 256) {
        int r = tid >> 4, k = tid & 15;
        *(__nv_bfloat16*)(Ap + r * 144 + k * 2) = __float2bfloat16((float)(r * 16 + k));
    }
    if (tid < 128) {
        int n = tid >> 4, k = tid & 15;
        *(__nv_bfloat16*)(Bp + n * 144 + k * 2) = __float2bfloat16((n == 0 && k == 0) ? 1.f : 0.f);
    }
    __syncthreads();
    if (wid == 0) {
        uint32_t a0 = *(uint32_t*)(Ap + g * 144 + tg * 4);
        uint32_t a1 = *(uint32_t*)(Ap + (g + 8) * 144 + tg * 4);
        uint32_t a2 = *(uint32_t*)(Ap + g * 144 + 16 + tg * 4);
        uint32_t a3 = *(uint32_t*)(Ap + (g + 8) * 144 + 16 + tg * 4);
        uint32_t b0 = *(uint32_t*)(Bp + g * 144 + tg * 4);
        uint32_t b1 = *(uint32_t*)(Bp + g * 144 + 16 + tg * 4);
        float d[4] = {0.f, 0.f, 0.f, 0.f};
        mma_bf16(d, a0, a1, a2, a3, b0, b1);
        int bad = (tg == 0) && (d[2] != (float)((g + 8) * 16));
        uint32_t anybad = __ballot_sync(~0u, bad);
        uint32_t lane_off = (uint32_t)(((lane >> 4) * 8 + (lane & 7)) * 144 + ((lane >> 3) & 1) * 16);
        uint32_t r0, r1, r2, r3;
        ldmx4(smem_u32(Ap) + lane_off, r0, r1, r2, r3);
        int bad2 = (r0 != a0) | (r1 != a2) | (r2 != a1) | (r3 != a3);
        uint32_t anybad2 = __ballot_sync(~0u, bad2);
        if (lane == 0) *s_flag = ((anybad != 0) ? 1 : 0) | ((anybad2 == 0) ? 2 : 0);
    }
    __syncthreads();
    int v = *s_flag;
    __syncthreads();
    return v;
}

// ============================================================
// K1: codebook MLP
// ============================================================
__global__ void mlp_kernel(const float* __restrict__ cbin,
                           const float* __restrict__ fc1w, const float* __restrict__ fc1b,
                           const float* __restrict__ fc2w, const float* __restrict__ fc2b) {
    __shared__ float row[DD];
    __shared__ float hs[HHID];
    int k = blockIdx.x, t = threadIdx.x;
    for (int d = t; d < DD; d += 128) row[d] = cbin[(size_t)k*DD + d];
    __syncthreads();
    float acc = fc1b[t];
    const float* w = fc1w + (size_t)t*DD;
    #pragma unroll 8
    for (int d = 0; d < DD; d++) acc += row[d] * w[d];
    hs[t] = sigm(acc);
    __syncthreads();
    for (int d = t; d < DD; d += 128) {
        float a = fc2b[d];
        const float* w2 = fc2w + (size_t)d*HHID;
        #pragma unroll 8
        for (int h = 0; h < HHID; h++) a += hs[h] * w2[h];
        g_ct[(size_t)k*DD + d] = a;
        g_cs[(size_t)k*DD + d] = sigm(a);
    }
}

// ============================================================
// K2: diag / off-diag outputs
// ============================================================
__global__ void diag_kernel(const float* __restrict__ causal, float* __restrict__ out) {
    int i = blockIdx.x;
    size_t base = (size_t)i * KC;
    for (int j = threadIdx.x; j < KC; j += blockDim.x) {
        float c = causal[base + j];
        bool dg = (j == i);
        out[O_CD + base + j] = dg ? c : 0.f;
        out[O_CM + base + j] = dg ? 0.f : c;
    }
}

// ============================================================
// K3: codebook GEMMs; mode 3 = fused modes 0+1 in one grid (8,32)
// ============================================================
__global__ __launch_bounds__(256) void gemm_cc(const float* __restrict__ A, int mode) {
    int by = blockIdx.y;
    if (mode == 3) { mode = (by < 16) ? 0 : 1; by &= 15; }
    const float* B = (mode == 2) ? g_c1 : g_cs;
    float* C = (mode == 0) ? g_c1 : (mode == 1 ? g_ccb : g_xcb);
    float diag_patch = (mode == 0) ? 0.f : 1.f;
    bool scale = (mode == 1);

    __shared__ __align__(16) float As[16][68];
    __shared__ __align__(16) float Bs[16][68];
    int tid = threadIdx.x, tx = tid & 15, ty = tid >> 4;
    int bm = by * 64, bn = blockIdx.x * 64;
    float acc[4][4] = {};
    for (int k0 = 0; k0 < KC; k0 += 16) {
        #pragma unroll
        for (int p = 0; p < 4; p++) {
            int e = tid + p * 256;
            int r = e >> 4, kk = e & 15;
            int grow = bm + r, gk = k0 + kk;
            As[kk][r] = (grow == gk) ? diag_patch : A[(size_t)grow*KC + gk];
        }
        #pragma unroll
        for (int p = 0; p < 4; p++) {
            int e = tid + p * 256;
            int kk = e >> 6, c = e & 63;
            int gk = k0 + kk;
            float bv = B[(size_t)gk*DD + bn + c];
            if (scale) bv *= A[(size_t)gk*KC + gk];
            Bs[kk][c] = bv;
        }
        __syncthreads();
        #pragma unroll
        for (int kk = 0; kk < 16; kk++) {
            float4 a = *(const float4*)&As[kk][ty*4];
            float4 b = *(const float4*)&Bs[kk][tx*4];
            float av[4] = {a.x, a.y, a.z, a.w};
            float bv[4] = {b.x, b.y, b.z, b.w};
            #pragma unroll
            for (int i = 0; i < 4; i++)
                #pragma unroll
                for (int j = 0; j < 4; j++)
                    acc[i][j] += av[i] * bv[j];
        }
        __syncthreads();
    }
    #pragma unroll
    for (int i = 0; i < 4; i++) {
        float4 v = make_float4(acc[i][0], acc[i][1], acc[i][2], acc[i][3]);
        *(float4*)&C[(size_t)(bm + ty*4 + i)*DD + bn + tx*4] = v;
    }
}

// ============================================================
// K4: g_cbn + reset flag counters
// ============================================================
__global__ void cbn_kernel() {
    if (blockIdx.x == 0 && threadIdx.x == 0) { g_nflagA = 0; g_nflagB = 0; }
    int k = blockIdx.x;
    float s = 0.f;
    for (int d = threadIdx.x; d < DD; d += 128) {
        float v = g_ccb[(size_t)k*DD + d];
        s += v * v;
    }
    #pragma unroll
    for (int off = 16; off; off >>= 1) s += __shfl_xor_sync(~0u, s, off);
    __shared__ float red[4];
    if ((threadIdx.x & 31) == 0) red[threadIdx.x >> 5] = s;
    __syncthreads();
    if (threadIdx.x == 0) g_cbn[k] = red[0] + red[1] + red[2] + red[3];
}

// ============================================================
// K4b: conversions
// ============================================================
#define X8   (NN*DD/8)
#define C8   (KC*DD/8)

__device__ __forceinline__ void split8(const float4* s, __nv_bfloat16* dh, __nv_bfloat16* dl, size_t j) {
    float4 f0 = s[0], f1 = s[1];
    float f[8] = {f0.x, f0.y, f0.z, f0.w, f1.x, f1.y, f1.z, f1.w};
    unsigned short hb[8], lb[8];
    #pragma unroll
    for (int e = 0; e < 8; e++) {
        __nv_bfloat16 h = __float2bfloat16(f[e]);
        float r = f[e] - __bfloat162float(h);
        __nv_bfloat16 l = __float2bfloat16(r);
        hb[e] = __nv_bfloat16_raw(h).x;
        lb[e] = __nv_bfloat16_raw(l).x;
    }
    ((uint4*)dh)[j] = make_uint4(hb[0]|(hb[1]<<16), hb[2]|(hb[3]<<16), hb[4]|(hb[5]<<16), hb[6]|(hb[7]<<16));
    ((uint4*)dl)[j] = make_uint4(lb[0]|(lb[1]<<16), lb[2]|(lb[3]<<16), lb[4]|(lb[5]<<16), lb[6]|(lb[7]<<16));
}
__device__ __forceinline__ void pack_f16(const float4* s, __half* df, size_t j) {
    float4 f0 = s[0], f1 = s[1];
    __half2 h0 = __floats2half2_rn(f0.x, f0.y);
    __half2 h1 = __floats2half2_rn(f0.z, f0.w);
    __half2 h2 = __floats2half2_rn(f1.x, f1.y);
    __half2 h3 = __floats2half2_rn(f1.z, f1.w);
    ((uint4*)df)[j] = make_uint4(*(uint32_t*)&h0, *(uint32_t*)&h1, *(uint32_t*)&h2, *(uint32_t*)&h3);
}

__global__ void convert_x(const float* __restrict__ x) {
    size_t i = (size_t)blockIdx.x * blockDim.x + threadIdx.x;
    if (i >= X8) return;
    const float4* s = (const float4*)x + i*2;
    split8(s, g_xh, g_xl, i);
    pack_f16(s, g_xf, i);
}
__global__ void convert_cbct() {
    size_t i = (size_t)blockIdx.x * blockDim.x + threadIdx.x;
    if (i >= 2 * C8) return;
    if (i < C8) split8((const float4*)g_ccb + i*2, g_ch, g_cl, i);
    else { size_t j = i - C8; pack_f16((const float4*)g_ct + j*2, g_ctf, j); }
}

// ============================================================
// K5: 3-pass split-bf16 tensor-core argmin with TOP-3 tracking.
// ============================================================
#define RSTRIDE   144
#define SUB_TB    (128 * RSTRIDE)
#define OFF_XH    0
#define OFF_XL    SUB_TB
#define OFF_CH    (2 * SUB_TB)
#define OFF_CL    (3 * SUB_TB)
#define STAGE_B3  (4 * SUB_TB)
#define OFF_CBN3  (2 * STAGE_B3)
#define SM3_DYN   (OFF_CBN3 + KC * 4)
#define AM_MARGIN 0.35f

__device__ __forceinline__ void stage_load3(uint32_t dst, int node0, int c0, int kt) {
    int tid = threadIdx.x;
    const __nv_bfloat16* srcs[4] = {
        g_xh + (size_t)node0 * DD, g_xl + (size_t)node0 * DD,
        g_ch + (size_t)c0 * DD,    g_cl + (size_t)c0 * DD };
    #pragma unroll
    for (int s = 0; s < 4; s++) {
        uint32_t d = dst + (uint32_t)s * SUB_TB;
        const __nv_bfloat16* src = srcs[s] + kt * 64;
        #pragma unroll
        for (int it = 0; it < 4; it++) {
            int idx = tid + it * 256;
            int row = idx >> 3, c8 = idx & 7;
            cp_async16(d + (uint32_t)row * RSTRIDE + (uint32_t)c8 * 16,
                       src + (size_t)row * DD + c8 * 8);
        }
    }
}

__global__ __launch_bounds__(256) void argmin_mma3() {
    extern __shared__ char sm[];
    float* scbn = (float*)(sm + OFF_CBN3);
    __shared__ int s_v1;

    int tid = threadIdx.x, lane = tid & 31, wid = tid >> 5;
    int g = lane >> 2, tg = lane & 3;
    int node0 = blockIdx.x * 128;

    int flags = mma_layout_probe(sm, &s_v1);
    int v1 = flags & 1;
    int use_ldm = (flags >> 1) & 1;
    uint32_t offA1 = v1 ? 16u : (uint32_t)(8 * RSTRIDE);
    uint32_t offA2 = v1 ? (uint32_t)(8 * RSTRIDE) : 16u;
    uint32_t lane_off = (uint32_t)(((lane >> 4) * 8 + (lane & 7)) * 144 + ((lane >> 3) & 1) * 16);

    for (int i = tid; i < KC; i += 256) scbn[i] = g_cbn[i];

    uint32_t smb = smem_u32(sm);
    stage_load3(smb, node0, 0, 0);
    CP_COMMIT();

    unsigned long long rs1[2], rs2[2], rs3[2];
    rs1[0] = rs1[1] = rs2[0] = rs2[1] = rs3[0] = rs3[1] = ~0ULL;

    float acc[16][4];

    for (int t = 0; t < 64; t++) {
        int c = t >> 3, kt = t & 7;
        if (kt == 0) {
            #pragma unroll
            for (int nf = 0; nf < 16; nf++)
                #pragma unroll
                for (int q = 0; q < 4; q++) acc[nf][q] = 0.f;
        }
        if (t < 63) {
            int tn = t + 1;
            stage_load3(smb + (uint32_t)(tn & 1) * STAGE_B3, node0, (tn >> 3) * 128, tn & 7);
            CP_COMMIT();
            CP_WAIT(1);
        } else {
            CP_WAIT(0);
        }
        __syncthreads();

        uint32_t StU = smb + (uint32_t)(t & 1) * STAGE_B3;
        const char* St = sm + (size_t)(t & 1) * STAGE_B3;
        const char* Axh = St + OFF_XH + (size_t)(wid * 16 + g) * RSTRIDE;
        const char* Axl = St + OFF_XL + (size_t)(wid * 16 + g) * RSTRIDE;

        if (use_ldm) {
            uint32_t BchU = StU + OFF_CH;
            uint32_t BclU = StU + OFF_CL;
            #pragma unroll
            for (int ks = 0; ks < 4; ks++) {
                int koff = (ks * 16 + tg * 2) * 2;
                uint32_t h0 = *(const uint32_t*)(Axh + koff);
                uint32_t h1 = *(const uint32_t*)(Axh + koff + offA1);
                uint32_t h2 = *(const uint32_t*)(Axh + koff + offA2);
                uint32_t h3 = *(const uint32_t*)(Axh + koff + 8 * RSTRIDE + 16);
                uint32_t l0 = *(const uint32_t*)(Axl + koff);
                uint32_t l1 = *(const uint32_t*)(Axl + koff + offA1);
                uint32_t l2 = *(const uint32_t*)(Axl + koff + offA2);
                uint32_t l3 = *(const uint32_t*)(Axl + koff + 8 * RSTRIDE + 16);
                uint32_t kso = (uint32_t)ks * 32 + lane_off;
                uint32_t b[8][2];
                #pragma unroll
                for (int j = 0; j < 4; j++)
                    ldmx4(BchU + (uint32_t)j * 2304 + kso, b[2*j][0], b[2*j][1], b[2*j+1][0], b[2*j+1][1]);
                #pragma unroll
                for (int nf = 0; nf < 8; nf++) {
                    mma_bf16(acc[nf], h0, h1, h2, h3, b[nf][0], b[nf][1]);
                    mma_bf16(acc[nf], l0, l1, l2, l3, b[nf][0], b[nf][1]);
                }
                #pragma unroll
                for (int j = 0; j < 4; j++)
                    ldmx4(BchU + (uint32_t)(j + 4) * 2304 + kso, b[2*j][0], b[2*j][1], b[2*j+1][0], b[2*j+1][1]);
                #pragma unroll
                for (int nf = 0; nf < 8; nf++) {
                    mma_bf16(acc[8 + nf], h0, h1, h2, h3, b[nf][0], b[nf][1]);
                    mma_bf16(acc[8 + nf], l0, l1, l2, l3, b[nf][0], b[nf][1]);
                }
                #pragma unroll
                for (int j = 0; j < 4; j++)
                    ldmx4(BclU + (uint32_t)j * 2304 + kso, b[2*j][0], b[2*j][1], b[2*j+1][0], b[2*j+1][1]);
                #pragma unroll
                for (int nf = 0; nf < 8; nf++)
                    mma_bf16(acc[nf], h0, h1, h2, h3, b[nf][0], b[nf][1]);
                #pragma unroll
                for (int j = 0; j < 4; j++)
                    ldmx4(BclU + (uint32_t)(j + 4) * 2304 + kso, b[2*j][0], b[2*j][1], b[2*j+1][0], b[2*j+1][1]);
                #pragma unroll
                for (int nf = 0; nf < 8; nf++)
                    mma_bf16(acc[8 + nf], h0, h1, h2, h3, b[nf][0], b[nf][1]);
            }
        } else {
            const char* Bch = St + OFF_CH + (size_t)g * RSTRIDE;
            const char* Bcl = St + OFF_CL + (size_t)g * RSTRIDE;
            #pragma unroll
            for (int ks = 0; ks < 4; ks++) {
                int koff = (ks * 16 + tg * 2) * 2;
                uint32_t h0 = *(const uint32_t*)(Axh + koff);
                uint32_t h1 = *(const uint32_t*)(Axh + koff + offA1);
                uint32_t h2 = *(const uint32_t*)(Axh + koff + offA2);
                uint32_t h3 = *(const uint32_t*)(Axh + koff + 8 * RSTRIDE + 16);
                uint32_t l0 = *(const uint32_t*)(Axl + koff);
                uint32_t l1 = *(const uint32_t*)(Axl + koff + offA1);
                uint32_t l2 = *(const uint32_t*)(Axl + koff + offA2);
                uint32_t l3 = *(const uint32_t*)(Axl + koff + 8 * RSTRIDE + 16);
                int kb = ks * 32 + tg * 4;
                #pragma unroll
                for (int nf = 0; nf < 16; nf++) {
                    size_t bro = (size_t)(nf * 8) * RSTRIDE + kb;
                    uint32_t bh0 = *(const uint32_t*)(Bch + bro);
                    uint32_t bh1 = *(const uint32_t*)(Bch + bro + 16);
                    uint32_t bl0 = *(const uint32_t*)(Bcl + bro);
                    uint32_t bl1 = *(const uint32_t*)(Bcl + bro + 16);
                    mma_bf16(acc[nf], h0, h1, h2, h3, bh0, bh1);
                    mma_bf16(acc[nf], h0, h1, h2, h3, bl0, bl1);
                    mma_bf16(acc[nf], l0, l1, l2, l3, bh0, bh1);
                }
            }
        }
        __syncthreads();

        if (kt == 7) {
            // top-3 epilogue for chunk c
            #pragma unroll
            for (int h = 0; h < 2; h++) {
                unsigned long long s1 = ~0ULL, s2 = ~0ULL, s3 = ~0ULL;
                #pragma unroll
                for (int nf = 0; nf < 16; nf++) {
                    #pragma unroll
                    for (int q = 0; q < 2; q++) {
                        int code = c * 128 + nf * 8 + tg * 2 + q;
                        float sc = scbn[code] - 2.f * acc[nf][h * 2 + q];
                        unsigned long long p = ((unsigned long long)fkey(sc) << 32) | (uint32_t)code;
                        ins3(s1, s2, s3, p);
                    }
                }
                #pragma unroll
                for (int off = 1; off <= 2; off <<= 1) {
                    unsigned long long o1 = __shfl_xor_sync(~0u, s1, off);
                    unsigned long long o2 = __shfl_xor_sync(~0u, s2, off);
                    unsigned long long o3 = __shfl_xor_sync(~0u, s3, off);
                    ins3(s1, s2, s3, o1);
                    ins3(s1, s2, s3, o2);
                    ins3(s1, s2, s3, o3);
                }
                ins3(rs1[h], rs2[h], rs3[h], s1);
                ins3(rs1[h], rs2[h], rs3[h], s2);
                ins3(rs1[h], rs2[h], rs3[h], s3);
            }
        }
    }

    if (tg == 0) {
        #pragma unroll
        for (int h = 0; h < 2; h++) {
            int node = node0 + wid * 16 + h * 8 + g;
            int c1 = (int)(rs1[h] & 0xFFFFFFFFu);
            g_idx[node] = c1;
            float f1 = funkey((uint32_t)(rs1[h] >> 32));
            float f2 = funkey((uint32_t)(rs2[h] >> 32));
            float f3 = funkey((uint32_t)(rs3[h] >> 32));
            if (!(f3 - f1 >= AM_MARGIN)) {
                int p = atomicAdd(&g_nflagB, 1);      // 3-way cluster: full scan
                g_flagB[p] = node;
            } else if (!(f2 - f1 >= AM_MARGIN)) {
                int c2 = (int)(rs2[h] & 0xFFFFFFFFu); // pair: exact 2-way compare
                int p = atomicAdd(&g_nflagA, 1);
                g_flagA[p] = node;
                g_flagAC[p] = (c1 & 0xFFFF) | (c2 << 16);
            }
        }
    }
}

// ============================================================
// K5a: pairwise exact refine — one warp per flagged node, 2 codes only
// ============================================================
__global__ __launch_bounds__(256) void refineA(const float* __restrict__ x) {
    int lane = threadIdx.x & 31;
    int gw = (blockIdx.x * blockDim.x + threadIdx.x) >> 5;
    int nw = (gridDim.x * blockDim.x) >> 5;
    int n = g_nflagA;
    for (int f = gw; f < n; f += nw) {
        int node = g_flagA[f];
        int cc = g_flagAC[f];
        int c1 = cc & 0xFFFF, c2 = (cc >> 16) & 0xFFFF;
        const float4* xr = (const float4*)(x + (size_t)node * DD);
        const float4* b1 = (const float4*)(g_ccb + (size_t)c1 * DD);
        const float4* b2 = (const float4*)(g_ccb + (size_t)c2 * DD);
        float d1 = 0.f, d2 = 0.f;
        #pragma unroll
        for (int j = 0; j < 4; j++) {
            int q = lane + j * 32;
            float4 xv = xr[q], v1 = b1[q], v2 = b2[q];
            d1 += xv.x*v1.x + xv.y*v1.y + xv.z*v1.z + xv.w*v1.w;
            d2 += xv.x*v2.x + xv.y*v2.y + xv.z*v2.z + xv.w*v2.w;
        }
        #pragma unroll
        for (int off = 16; off; off >>= 1) {
            d1 += __shfl_xor_sync(~0u, d1, off);
            d2 += __shfl_xor_sync(~0u, d2, off);
        }
        if (lane == 0) {
            float s1 = g_cbn[c1] - 2.f * d1;
            float s2 = g_cbn[c2] - 2.f * d2;
            unsigned long long p1 = ((unsigned long long)fkey(s1) << 32) | (uint32_t)c1;
            unsigned long long p2 = ((unsigned long long)fkey(s2) << 32) | (uint32_t)c2;
            g_idx[node] = (int)(((p1 < p2) ? p1 : p2) & 0xFFFFFFFFu);
        }
    }
}

// ============================================================
// K5b: full-scan exact refine (3-way clusters; expected ~0)
// ============================================================
__global__ __launch_bounds__(256) void refineB(const float* __restrict__ x) {
    __shared__ __align__(16) float xs[DD];
    __shared__ unsigned long long sbest;
    int tid = threadIdx.x;
    int nf = g_nflagB;
    for (int f = blockIdx.x; f < nf; f += gridDim.x) {
        int node = g_flagB[f];
        if (tid < 128) ((float4*)xs)[tid] = ((const float4*)x)[(size_t)node * 128 + tid];
        if (tid == 0) sbest = ~0ULL;
        __syncthreads();
        unsigned long long best = ~0ULL;
        #pragma unroll
        for (int cc = 0; cc < 4; cc++) {
            int code = tid + cc * 256;
            const float4* cb = (const float4*)(g_ccb + (size_t)code * DD);
            float dot = 0.f;
            #pragma unroll 8
            for (int q = 0; q < 128; q++) {
                float4 a = ((const float4*)xs)[q], b = cb[q];
                dot += a.x * b.x + a.y * b.y + a.z * b.z + a.w * b.w;
            }
            float sc = g_cbn[code] - 2.f * dot;
            unsigned long long p = ((unsigned long long)fkey(sc) << 32) | (uint32_t)code;
            if (p < best) best = p;
        }
        atomicMin(&sbest, best);
        __syncthreads();
        if (tid == 0) g_idx[node] = (int)(sbest & 0xFFFFFFFFu);
        __syncthreads();
    }
}

// ============================================================
// K6: per node: x copy, z gather, inv norms
// ============================================================
__global__ void node_kernel(const float* __restrict__ x, float* __restrict__ out) {
    int n = blockIdx.x, t = threadIdx.x;
    float4 xv = ((const float4*)x)[(size_t)n*128 + t];
    ((float4*)(out + O_X))[(size_t)n*128 + t] = xv;
    int code = g_idx[n];
    float4 zv = ((const float4*)g_ct)[(size_t)code*128 + t];
    ((float4*)(out + O_Z))[(size_t)n*128 + t] = zv;
    float sx = xv.x*xv.x + xv.y*xv.y + xv.z*xv.z + xv.w*xv.w;
    float sz = zv.x*zv.x + zv.y*zv.y + zv.z*zv.z + zv.w*zv.w;
    #pragma unroll
    for (int off = 16; off; off >>= 1) {
        sx += __shfl_xor_sync(~0u, sx, off);
        sz += __shfl_xor_sync(~0u, sz, off);
    }
    __shared__ float rx[4], rz[4];
    if ((t & 31) == 0) { rx[t >> 5] = sx; rz[t >> 5] = sz; }
    __syncthreads();
    if (t == 0) {
        float nx = sqrtf(rx[0] + rx[1] + rx[2] + rx[3]);
        float nz = sqrtf(rz[0] + rz[1] + rz[2] + rz[3]);
        g_invnx[n] = 1.f / fmaxf(nx, 1e-12f);
        g_invnz[n] = 1.f / fmaxf(nz, 1e-12f);
    }
}

// ============================================================
// K7: pooled means + classifier heads
// ============================================================
__global__ __launch_bounds__(256) void pool_kernel(const float* __restrict__ x,
                                                   const float* __restrict__ clsw,
                                                   const float* __restrict__ clsb,
                                                   float* __restrict__ out) {
    int g = blockIdx.x, t = threadIdx.x;
    __shared__ int idxs[NPG];
    __shared__ float sp[3][DD];
    if (t < NPG) idxs[t] = g_idx[g*NPG + t];
    __syncthreads();
    for (int d = t; d < DD; d += 256) {
        float ax = 0.f, ac = 0.f, ak = 0.f;
        #pragma unroll 4
        for (int nn = 0; nn < NPG; nn++) {
            ax += x[(size_t)(g*NPG + nn)*DD + d];
            int c = idxs[nn];
            ac += g_ccb[(size_t)c*DD + d];
            ak += g_xcb[(size_t)c*DD + d];
        }
        float px = ax * (1.f/128.f);
        float pc = px + ac * (1.f/128.f);
        float pk = ak * (1.f/128.f);
        out[O_PX + (size_t)g*DD + d] = px;
        out[O_PC + (size_t)g*DD + d] = pc;
        sp[0][d] = pc; sp[1][d] = pk; sp[2][d] = px;
    }
    __syncthreads();
    int lane = t & 31, w = t >> 5;
    for (int job = w; job < 30; job += 8) {
        int vec = job / 10, cc = job % 10;
        float a = 0.f;
        for (int d = lane; d < DD; d += 32) a += sp[vec][d] * clsw[(size_t)cc*DD + d];
        #pragma unroll
        for (int off = 16; off; off >>= 1) a += __shfl_xor_sync(~0u, a, off);
        if (lane == 0) {
            long long base = (vec == 0) ? O_CPRE : (vec == 1 ? O_KPRE : O_YPRE);
            out[base + (size_t)g*TCLS + cc] = a + clsb[cc];
        }
    }
}

// ============================================================
// K8: adjacency via single-pass fp16 mma (Gram), normalize in epilogue.
// ============================================================
#define AJ_STAGE  SUB_TB
#define AJ_DYN    (2 * AJ_STAGE)

__device__ __forceinline__ void adj_stage(uint32_t dst, const __half* base, const int* idx_s,
                                          int node0, int mode, int kt) {
    int tid = threadIdx.x;
    #pragma unroll
    for (int it = 0; it < 4; it++) {
        int e = tid + it * 256;
        int row = e >> 3, c8 = e & 7;
        size_t roff = mode ? (size_t)idx_s[row] : (size_t)(node0 + row);
        cp_async16(dst + (uint32_t)row * RSTRIDE + (uint32_t)c8 * 16,
                   base + roff * DD + kt * 64 + c8 * 8);
    }
}

__global__ __launch_bounds__(256) void adj_mma(float* __restrict__ out) {
    extern __shared__ char sm[];
    __shared__ int s_v1;
    __shared__ int idx_s[NPG];
    __shared__ float invn_s[NPG];

    int tid = threadIdx.x, lane = tid & 31, wid = tid >> 5;
    int g = lane >> 2, tg = lane & 3;
    int b = blockIdx.x;
    int mode = b >> 9;
    int gr = b & 511;
    int node0 = gr * 128;

    int flags = mma_layout_probe(sm, &s_v1);
    int v1 = flags & 1;
    uint32_t offA1 = v1 ? 16u : (uint32_t)(8 * RSTRIDE);
    uint32_t offA2 = v1 ? (uint32_t)(8 * RSTRIDE) : 16u;

    if (tid < NPG) {
        idx_s[tid]  = g_idx[node0 + tid];
        invn_s[tid] = mode ? g_invnz[node0 + tid] : g_invnx[node0 + tid];
    }
    __syncthreads();

    const __half* base = mode ? g_ctf : g_xf;
    uint32_t smb = smem_u32(sm);

    adj_stage(smb, base, idx_s, node0, mode, 0);
    CP_COMMIT();

    float acc[16][4];
    #pragma unroll
    for (int nf = 0; nf < 16; nf++)
        #pragma unroll
        for (int q = 0; q < 4; q++) acc[nf][q] = 0.f;

    for (int kt = 0; kt < 8; kt++) {
        if (kt < 7) {
            adj_stage(smb + (uint32_t)((kt + 1) & 1) * AJ_STAGE, base, idx_s, node0, mode, kt + 1);
            CP_COMMIT();
            CP_WAIT(1);
        } else {
            CP_WAIT(0);
        }
        __syncthreads();

        const char* St = sm + (size_t)(kt & 1) * AJ_STAGE;
        const char* Ah = St + (size_t)(wid * 16 + g) * RSTRIDE;
        #pragma unroll
        for (int ks = 0; ks < 4; ks++) {
            int koff = (ks * 16 + tg * 2) * 2;
            uint32_t a0 = *(const uint32_t*)(Ah + koff);
            uint32_t a1 = *(const uint32_t*)(Ah + koff + offA1);
            uint32_t a2 = *(const uint32_t*)(Ah + koff + offA2);
            uint32_t a3 = *(const uint32_t*)(Ah + koff + 8 * RSTRIDE + 16);
            int kb = ks * 32 + tg * 4;
            #pragma unroll
            for (int nf = 0; nf < 16; nf++) {
                size_t bro = (size_t)(nf * 8 + g) * RSTRIDE + kb;
                uint32_t b0 = *(const uint32_t*)(St + bro);
                uint32_t b1 = *(const uint32_t*)(St + bro + 16);
                mma_f16(acc[nf], a0, a1, a2, a3, b0, b1);
            }
        }
        __syncthreads();
    }

    float* dst = out + (mode ? O_AR : O_AO) + (size_t)gr * (NPG * NPG);
    #pragma unroll
    for (int h = 0; h < 2; h++) {
        int r = wid * 16 + h * 8 + g;
        float invr = invn_s[r];
        #pragma unroll
        for (int nf = 0; nf < 16; nf++) {
            #pragma unroll
            for (int q = 0; q < 2; q++) {
                int c = nf * 8 + tg * 2 + q;
                dst[(size_t)r * NPG + c] = sigm10f(acc[nf][h * 2 + q] * invr * invn_s[c]);
            }
        }
    }
}

// ============================================================
extern "C" void kernel_launch(void* const* d_in, const int* in_sizes, int n_in,
                              void* d_out, int out_size) {
    const float* x      = (const float*)d_in[0];
    const float* cbin   = (const float*)d_in[2];
    const float* fc1w   = (const float*)d_in[3];
    const float* fc1b   = (const float*)d_in[4];
    const float* fc2w   = (const float*)d_in[5];
    const float* fc2b   = (const float*)d_in[6];
    const float* causal = (const float*)d_in[7];
    const float* clsw   = (const float*)d_in[8];
    const float* clsb   = (const float*)d_in[9];
    float* out = (float*)d_out;

    cudaFuncSetAttribute(argmin_mma3, cudaFuncAttributeMaxDynamicSharedMemorySize, SM3_DYN);
    cudaFuncSetAttribute(adj_mma,     cudaFuncAttributeMaxDynamicSharedMemorySize, AJ_DYN);

    diag_kernel<<<KC, 256>>>(causal, out);
    mlp_kernel<<<KC, 128>>>(cbin, fc1w, fc1b, fc2w, fc2b);
    gemm_cc<<<dim3(8, 32), 256>>>(causal, 3);           // fused: c1 + causal_cb
    cbn_kernel<<<KC, 128>>>();
    convert_cbct<<<(2 * C8) / 256, 256>>>();
    gemm_cc<<<dim3(8, 16), 256>>>(causal, 2);           // counter_cb
    convert_x<<<X8 / 256, 256>>>(x);
    argmin_mma3<<<NN / 128, 256, SM3_DYN>>>();
    refineA<<<64, 256>>>(x);
    refineB<<<64, 256>>>(x);
    node_kernel<<<NN, 128>>>(x, out);
    pool_kernel<<<GG, 256>>>(x, clsw, clsb, out);
    adj_mma<<<2 * GG, 256, AJ_DYN>>>(out);
}

// round 17
// speedup vs baseline: 1.4831x; 1.1085x over previous
#include <cuda_runtime.h>
#include <cuda_bf16.h>
#include <cuda_fp16.h>
#include <math.h>
#include <stdint.h>

// ---- fixed problem shapes ----
#define GG   512
#define NPG  128
#define NN   65536
#define DD   512
#define KC   1024
#define HHID 128
#define TCLS 10

// ---- device scratch ----
static __device__ float g_ct [KC*DD];
static __device__ float g_cs [KC*DD];
static __device__ float g_c1 [KC*DD];
static __device__ float g_ccb[KC*DD];
static __device__ float g_xcb[KC*DD];
static __device__ float g_cbn[KC];
static __device__ int   g_idx[NN];
static __device__ float g_invnx[NN];
static __device__ float g_invnz[NN];
static __device__ __half g_xh[NN*DD];    // f16(x)  (also used by adj)
static __device__ __half g_xl[NN*DD];    // f16(x - xh)  (exact residual)
static __device__ __half g_ch[KC*DD];    // f16(causal_cb)
static __device__ __half g_ctf[KC*DD];   // f16(ct) for adj
static __device__ int g_nflagA;          // pairwise refine queue
static __device__ int g_flagA[NN];
static __device__ int g_flagAC[NN];      // c1 | (c2<<16)
static __device__ int g_nflagB;          // full-scan refine queue
static __device__ int g_flagB[NN];

// ---- output offsets (floats) ----
#define O_CPRE 0LL
#define O_KPRE 5120LL
#define O_YPRE 10240LL
#define O_AO   15360LL
#define O_AR   8403968LL
#define O_Z    16792576LL
#define O_X    50347008LL
#define O_CD   83901440LL
#define O_CM   84950016LL
#define O_PC   85998592LL
#define O_PX   86260736LL

__device__ __forceinline__ float sigm(float v) { return 1.f / (1.f + expf(-v)); }
__device__ __forceinline__ float sigm10f(float v) { return 1.f / (1.f + __expf(-10.f * v)); }

// ---- portable tensor-core helpers ----
__device__ __forceinline__ uint32_t smem_u32(const void* p) {
    uint32_t a;
    asm("{ .reg .u64 t; cvta.to.shared.u64 t, %1; cvt.u32.u64 %0, t; }" : "=r"(a) : "l"(p));
    return a;
}
__device__ __forceinline__ void mma_bf16(float* d, uint32_t a0, uint32_t a1, uint32_t a2, uint32_t a3,
                                         uint32_t b0, uint32_t b1) {
    asm volatile("mma.sync.aligned.m16n8k16.row.col.f32.bf16.bf16.f32 "
                 "{%0,%1,%2,%3}, {%4,%5,%6,%7}, {%8,%9}, {%0,%1,%2,%3};"
                 : "+f"(d[0]), "+f"(d[1]), "+f"(d[2]), "+f"(d[3])
                 : "r"(a0), "r"(a1), "r"(a2), "r"(a3), "r"(b0), "r"(b1));
}
__device__ __forceinline__ void mma_f16(float* d, uint32_t a0, uint32_t a1, uint32_t a2, uint32_t a3,
                                        uint32_t b0, uint32_t b1) {
    asm volatile("mma.sync.aligned.m16n8k16.row.col.f32.f16.f16.f32 "
                 "{%0,%1,%2,%3}, {%4,%5,%6,%7}, {%8,%9}, {%0,%1,%2,%3};"
                 : "+f"(d[0]), "+f"(d[1]), "+f"(d[2]), "+f"(d[3])
                 : "r"(a0), "r"(a1), "r"(a2), "r"(a3), "r"(b0), "r"(b1));
}
__device__ __forceinline__ void ldmx4(uint32_t a, uint32_t& r0, uint32_t& r1, uint32_t& r2, uint32_t& r3) {
    asm volatile("ldmatrix.sync.aligned.m8n8.x4.shared.b16 {%0,%1,%2,%3}, [%4];"
                 : "=r"(r0), "=r"(r1), "=r"(r2), "=r"(r3) : "r"(a));
}
__device__ __forceinline__ void cp_async16(uint32_t dst, const void* src) {
    asm volatile("cp.async.cg.shared.global [%0], [%1], 16;" :: "r"(dst), "l"(src) : "memory");
}
#define CP_COMMIT()  asm volatile("cp.async.commit_group;" ::: "memory")
#define CP_WAIT(n)   asm volatile("cp.async.wait_group %0;" :: "n"(n) : "memory")

__device__ __forceinline__ uint32_t fkey(float f) {
    uint32_t b = __float_as_uint(f);
    return (b & 0x80000000u) ? ~b : (b | 0x80000000u);
}
__device__ __forceinline__ float funkey(uint32_t k) {
    uint32_t b = (k & 0x80000000u) ? (k & 0x7FFFFFFFu) : ~k;
    return __uint_as_float(b);
}
__device__ __forceinline__ void ins3(unsigned long long& s1, unsigned long long& s2,
                                     unsigned long long& s3, unsigned long long v) {
    if (v < s1)      { s3 = s2; s2 = s1; s1 = v; }
    else if (v < s2) { s3 = s2; s2 = v; }
    else if (v < s3) { s3 = v; }
}

// Probe: bit0 = A-frag middle registers swapped (v1); bit1 = ldmatrix mapping OK.
// Fragment layout is identical for f16/bf16 b16 operands.
__device__ __forceinline__ int mma_layout_probe(char* sm, int* s_flag) {
    int tid = threadIdx.x, lane = tid & 31, wid = tid >> 5;
    int g = lane >> 2, tg = lane & 3;
    char* Ap = sm;
    char* Bp = sm + 8192;
    if (tid < 256) {
        int r = tid >> 4, k = tid & 15;
        *(__nv_bfloat16*)(Ap + r * 144 + k * 2) = __float2bfloat16((float)(r * 16 + k));
    }
    if (tid < 128) {
        int n = tid >> 4, k = tid & 15;
        *(__nv_bfloat16*)(Bp + n * 144 + k * 2) = __float2bfloat16((n == 0 && k == 0) ? 1.f : 0.f);
    }
    __syncthreads();
    if (wid == 0) {
        uint32_t a0 = *(uint32_t*)(Ap + g * 144 + tg * 4);
        uint32_t a1 = *(uint32_t*)(Ap + (g + 8) * 144 + tg * 4);
        uint32_t a2 = *(uint32_t*)(Ap + g * 144 + 16 + tg * 4);
        uint32_t a3 = *(uint32_t*)(Ap + (g + 8) * 144 + 16 + tg * 4);
        uint32_t b0 = *(uint32_t*)(Bp + g * 144 + tg * 4);
        uint32_t b1 = *(uint32_t*)(Bp + g * 144 + 16 + tg * 4);
        float d[4] = {0.f, 0.f, 0.f, 0.f};
        mma_bf16(d, a0, a1, a2, a3, b0, b1);
        int bad = (tg == 0) && (d[2] != (float)((g + 8) * 16));
        uint32_t anybad = __ballot_sync(~0u, bad);
        uint32_t lane_off = (uint32_t)(((lane >> 4) * 8 + (lane & 7)) * 144 + ((lane >> 3) & 1) * 16);
        uint32_t r0, r1, r2, r3;
        ldmx4(smem_u32(Ap) + lane_off, r0, r1, r2, r3);
        int bad2 = (r0 != a0) | (r1 != a2) | (r2 != a1) | (r3 != a3);
        uint32_t anybad2 = __ballot_sync(~0u, bad2);
        if (lane == 0) *s_flag = ((anybad != 0) ? 1 : 0) | ((anybad2 == 0) ? 2 : 0);
    }
    __syncthreads();
    int v = *s_flag;
    __syncthreads();
    return v;
}

// ============================================================
// K1: codebook MLP
// ============================================================
__global__ void mlp_kernel(const float* __restrict__ cbin,
                           const float* __restrict__ fc1w, const float* __restrict__ fc1b,
                           const float* __restrict__ fc2w, const float* __restrict__ fc2b) {
    __shared__ float row[DD];
    __shared__ float hs[HHID];
    int k = blockIdx.x, t = threadIdx.x;
    for (int d = t; d < DD; d += 128) row[d] = cbin[(size_t)k*DD + d];
    __syncthreads();
    float acc = fc1b[t];
    const float* w = fc1w + (size_t)t*DD;
    #pragma unroll 8
    for (int d = 0; d < DD; d++) acc += row[d] * w[d];
    hs[t] = sigm(acc);
    __syncthreads();
    for (int d = t; d < DD; d += 128) {
        float a = fc2b[d];
        const float* w2 = fc2w + (size_t)d*HHID;
        #pragma unroll 8
        for (int h = 0; h < HHID; h++) a += hs[h] * w2[h];
        g_ct[(size_t)k*DD + d] = a;
        g_cs[(size_t)k*DD + d] = sigm(a);
    }
}

// ============================================================
// K2: diag / off-diag outputs
// ============================================================
__global__ void diag_kernel(const float* __restrict__ causal, float* __restrict__ out) {
    int i = blockIdx.x;
    size_t base = (size_t)i * KC;
    for (int j = threadIdx.x; j < KC; j += blockDim.x) {
        float c = causal[base + j];
        bool dg = (j == i);
        out[O_CD + base + j] = dg ? c : 0.f;
        out[O_CM + base + j] = dg ? 0.f : c;
    }
}

// ============================================================
// K3: codebook GEMMs; mode 3 = fused modes 0+1 in one grid (8,32)
// ============================================================
__global__ __launch_bounds__(256) void gemm_cc(const float* __restrict__ A, int mode) {
    int by = blockIdx.y;
    if (mode == 3) { mode = (by < 16) ? 0 : 1; by &= 15; }
    const float* B = (mode == 2) ? g_c1 : g_cs;
    float* C = (mode == 0) ? g_c1 : (mode == 1 ? g_ccb : g_xcb);
    float diag_patch = (mode == 0) ? 0.f : 1.f;
    bool scale = (mode == 1);

    __shared__ __align__(16) float As[16][68];
    __shared__ __align__(16) float Bs[16][68];
    int tid = threadIdx.x, tx = tid & 15, ty = tid >> 4;
    int bm = by * 64, bn = blockIdx.x * 64;
    float acc[4][4] = {};
    for (int k0 = 0; k0 < KC; k0 += 16) {
        #pragma unroll
        for (int p = 0; p < 4; p++) {
            int e = tid + p * 256;
            int r = e >> 4, kk = e & 15;
            int grow = bm + r, gk = k0 + kk;
            As[kk][r] = (grow == gk) ? diag_patch : A[(size_t)grow*KC + gk];
        }
        #pragma unroll
        for (int p = 0; p < 4; p++) {
            int e = tid + p * 256;
            int kk = e >> 6, c = e & 63;
            int gk = k0 + kk;
            float bv = B[(size_t)gk*DD + bn + c];
            if (scale) bv *= A[(size_t)gk*KC + gk];
            Bs[kk][c] = bv;
        }
        __syncthreads();
        #pragma unroll
        for (int kk = 0; kk < 16; kk++) {
            float4 a = *(const float4*)&As[kk][ty*4];
            float4 b = *(const float4*)&Bs[kk][tx*4];
            float av[4] = {a.x, a.y, a.z, a.w};
            float bv[4] = {b.x, b.y, b.z, b.w};
            #pragma unroll
            for (int i = 0; i < 4; i++)
                #pragma unroll
                for (int j = 0; j < 4; j++)
                    acc[i][j] += av[i] * bv[j];
        }
        __syncthreads();
    }
    #pragma unroll
    for (int i = 0; i < 4; i++) {
        float4 v = make_float4(acc[i][0], acc[i][1], acc[i][2], acc[i][3]);
        *(float4*)&C[(size_t)(bm + ty*4 + i)*DD + bn + tx*4] = v;
    }
}

// ============================================================
// K4: g_cbn + reset flag counters
// ============================================================
__global__ void cbn_kernel() {
    if (blockIdx.x == 0 && threadIdx.x == 0) { g_nflagA = 0; g_nflagB = 0; }
    int k = blockIdx.x;
    float s = 0.f;
    for (int d = threadIdx.x; d < DD; d += 128) {
        float v = g_ccb[(size_t)k*DD + d];
        s += v * v;
    }
    #pragma unroll
    for (int off = 16; off; off >>= 1) s += __shfl_xor_sync(~0u, s, off);
    __shared__ float red[4];
    if ((threadIdx.x & 31) == 0) red[threadIdx.x >> 5] = s;
    __syncthreads();
    if (threadIdx.x == 0) g_cbn[k] = red[0] + red[1] + red[2] + red[3];
}

// ============================================================
// K4b: conversions (f16 split for x; f16 for cb, ct)
// ============================================================
#define X8   (NN*DD/8)
#define C8   (KC*DD/8)

__device__ __forceinline__ void split8h(const float4* s, __half* dh, __half* dl, size_t j) {
    float4 f0 = s[0], f1 = s[1];
    float f[8] = {f0.x, f0.y, f0.z, f0.w, f1.x, f1.y, f1.z, f1.w};
    unsigned short hb[8], lb[8];
    #pragma unroll
    for (int e = 0; e < 8; e++) {
        __half h = __float2half_rn(f[e]);
        float r = f[e] - __half2float(h);
        __half l = __float2half_rn(r);
        hb[e] = __half_raw(h).x;
        lb[e] = __half_raw(l).x;
    }
    ((uint4*)dh)[j] = make_uint4(hb[0]|(hb[1]<<16), hb[2]|(hb[3]<<16), hb[4]|(hb[5]<<16), hb[6]|(hb[7]<<16));
    ((uint4*)dl)[j] = make_uint4(lb[0]|(lb[1]<<16), lb[2]|(lb[3]<<16), lb[4]|(lb[5]<<16), lb[6]|(lb[7]<<16));
}
__device__ __forceinline__ void pack_f16(const float4* s, __half* df, size_t j) {
    float4 f0 = s[0], f1 = s[1];
    __half2 h0 = __floats2half2_rn(f0.x, f0.y);
    __half2 h1 = __floats2half2_rn(f0.z, f0.w);
    __half2 h2 = __floats2half2_rn(f1.x, f1.y);
    __half2 h3 = __floats2half2_rn(f1.z, f1.w);
    ((uint4*)df)[j] = make_uint4(*(uint32_t*)&h0, *(uint32_t*)&h1, *(uint32_t*)&h2, *(uint32_t*)&h3);
}

__global__ void convert_x(const float* __restrict__ x) {
    size_t i = (size_t)blockIdx.x * blockDim.x + threadIdx.x;
    if (i >= X8) return;
    split8h((const float4*)x + i*2, g_xh, g_xl, i);
}
__global__ void convert_cbct() {
    size_t i = (size_t)blockIdx.x * blockDim.x + threadIdx.x;
    if (i >= 2 * C8) return;
    if (i < C8) pack_f16((const float4*)g_ccb + i*2, g_ch, i);
    else { size_t j = i - C8; pack_f16((const float4*)g_ct + j*2, g_ctf, j); }
}

// ============================================================
// K5: 2-pass split-f16 tensor-core argmin with TOP-3 tracking.
// Stage = {xh, xl, ch} tiles (3 x 18432 B), double-buffered.
// ============================================================
#define RSTRIDE   144
#define SUB_TB    (128 * RSTRIDE)
#define OFF_XH    0
#define OFF_XL    SUB_TB
#define OFF_CH    (2 * SUB_TB)
#define STAGE_B3  (3 * SUB_TB)             // 55296
#define OFF_CBN3  (2 * STAGE_B3)           // 110592
#define SM3_DYN   (OFF_CBN3 + KC * 4)      // 114688
#define AM_MARGIN 1.25f

__device__ __forceinline__ void stage_load3(uint32_t dst, int node0, int c0, int kt) {
    int tid = threadIdx.x;
    const __half* srcs[3] = {
        g_xh + (size_t)node0 * DD, g_xl + (size_t)node0 * DD, g_ch + (size_t)c0 * DD };
    #pragma unroll
    for (int s = 0; s < 3; s++) {
        uint32_t d = dst + (uint32_t)s * SUB_TB;
        const __half* src = srcs[s] + kt * 64;
        #pragma unroll
        for (int it = 0; it < 4; it++) {
            int idx = tid + it * 256;
            int row = idx >> 3, c8 = idx & 7;
            cp_async16(d + (uint32_t)row * RSTRIDE + (uint32_t)c8 * 16,
                       src + (size_t)row * DD + c8 * 8);
        }
    }
}

__global__ __launch_bounds__(256) void argmin_mma3() {
    extern __shared__ char sm[];
    float* scbn = (float*)(sm + OFF_CBN3);
    __shared__ int s_v1;

    int tid = threadIdx.x, lane = tid & 31, wid = tid >> 5;
    int g = lane >> 2, tg = lane & 3;
    int node0 = blockIdx.x * 128;

    int flags = mma_layout_probe(sm, &s_v1);
    int v1 = flags & 1;
    int use_ldm = (flags >> 1) & 1;
    uint32_t offA1 = v1 ? 16u : (uint32_t)(8 * RSTRIDE);
    uint32_t offA2 = v1 ? (uint32_t)(8 * RSTRIDE) : 16u;
    uint32_t lane_off = (uint32_t)(((lane >> 4) * 8 + (lane & 7)) * 144 + ((lane >> 3) & 1) * 16);

    for (int i = tid; i < KC; i += 256) scbn[i] = g_cbn[i];

    uint32_t smb = smem_u32(sm);
    stage_load3(smb, node0, 0, 0);
    CP_COMMIT();

    unsigned long long rs1[2], rs2[2], rs3[2];
    rs1[0] = rs1[1] = rs2[0] = rs2[1] = rs3[0] = rs3[1] = ~0ULL;

    float acc[16][4];

    for (int t = 0; t < 64; t++) {
        int c = t >> 3, kt = t & 7;
        if (kt == 0) {
            #pragma unroll
            for (int nf = 0; nf < 16; nf++)
                #pragma unroll
                for (int q = 0; q < 4; q++) acc[nf][q] = 0.f;
        }
        if (t < 63) {
            int tn = t + 1;
            stage_load3(smb + (uint32_t)(tn & 1) * STAGE_B3, node0, (tn >> 3) * 128, tn & 7);
            CP_COMMIT();
            CP_WAIT(1);
        } else {
            CP_WAIT(0);
        }
        __syncthreads();

        uint32_t StU = smb + (uint32_t)(t & 1) * STAGE_B3;
        const char* St = sm + (size_t)(t & 1) * STAGE_B3;
        const char* Axh = St + OFF_XH + (size_t)(wid * 16 + g) * RSTRIDE;
        const char* Axl = St + OFF_XL + (size_t)(wid * 16 + g) * RSTRIDE;

        if (use_ldm) {
            uint32_t BchU = StU + OFF_CH;
            #pragma unroll
            for (int ks = 0; ks < 4; ks++) {
                int koff = (ks * 16 + tg * 2) * 2;
                uint32_t h0 = *(const uint32_t*)(Axh + koff);
                uint32_t h1 = *(const uint32_t*)(Axh + koff + offA1);
                uint32_t h2 = *(const uint32_t*)(Axh + koff + offA2);
                uint32_t h3 = *(const uint32_t*)(Axh + koff + 8 * RSTRIDE + 16);
                uint32_t l0 = *(const uint32_t*)(Axl + koff);
                uint32_t l1 = *(const uint32_t*)(Axl + koff + offA1);
                uint32_t l2 = *(const uint32_t*)(Axl + koff + offA2);
                uint32_t l3 = *(const uint32_t*)(Axl + koff + 8 * RSTRIDE + 16);
                uint32_t kso = (uint32_t)ks * 32 + lane_off;
                uint32_t b[8][2];
                #pragma unroll
                for (int j = 0; j < 4; j++)
                    ldmx4(BchU + (uint32_t)j * 2304 + kso, b[2*j][0], b[2*j][1], b[2*j+1][0], b[2*j+1][1]);
                #pragma unroll
                for (int nf = 0; nf < 8; nf++) {
                    mma_f16(acc[nf], h0, h1, h2, h3, b[nf][0], b[nf][1]);
                    mma_f16(acc[nf], l0, l1, l2, l3, b[nf][0], b[nf][1]);
                }
                #pragma unroll
                for (int j = 0; j < 4; j++)
                    ldmx4(BchU + (uint32_t)(j + 4) * 2304 + kso, b[2*j][0], b[2*j][1], b[2*j+1][0], b[2*j+1][1]);
                #pragma unroll
                for (int nf = 0; nf < 8; nf++) {
                    mma_f16(acc[8 + nf], h0, h1, h2, h3, b[nf][0], b[nf][1]);
                    mma_f16(acc[8 + nf], l0, l1, l2, l3, b[nf][0], b[nf][1]);
                }
            }
        } else {
            const char* Bch = St + OFF_CH + (size_t)g * RSTRIDE;
            #pragma unroll
            for (int ks = 0; ks < 4; ks++) {
                int koff = (ks * 16 + tg * 2) * 2;
                uint32_t h0 = *(const uint32_t*)(Axh + koff);
                uint32_t h1 = *(const uint32_t*)(Axh + koff + offA1);
                uint32_t h2 = *(const uint32_t*)(Axh + koff + offA2);
                uint32_t h3 = *(const uint32_t*)(Axh + koff + 8 * RSTRIDE + 16);
                uint32_t l0 = *(const uint32_t*)(Axl + koff);
                uint32_t l1 = *(const uint32_t*)(Axl + koff + offA1);
                uint32_t l2 = *(const uint32_t*)(Axl + koff + offA2);
                uint32_t l3 = *(const uint32_t*)(Axl + koff + 8 * RSTRIDE + 16);
                int kb = ks * 32 + tg * 4;
                #pragma unroll
                for (int nf = 0; nf < 16; nf++) {
                    size_t bro = (size_t)(nf * 8) * RSTRIDE + kb;
                    uint32_t bh0 = *(const uint32_t*)(Bch + bro);
                    uint32_t bh1 = *(const uint32_t*)(Bch + bro + 16);
                    mma_f16(acc[nf], h0, h1, h2, h3, bh0, bh1);
                    mma_f16(acc[nf], l0, l1, l2, l3, bh0, bh1);
                }
            }
        }
        __syncthreads();

        if (kt == 7) {
            #pragma unroll
            for (int h = 0; h < 2; h++) {
                unsigned long long s1 = ~0ULL, s2 = ~0ULL, s3 = ~0ULL;
                #pragma unroll
                for (int nf = 0; nf < 16; nf++) {
                    #pragma unroll
                    for (int q = 0; q < 2; q++) {
                        int code = c * 128 + nf * 8 + tg * 2 + q;
                        float sc = scbn[code] - 2.f * acc[nf][h * 2 + q];
                        unsigned long long p = ((unsigned long long)fkey(sc) << 32) | (uint32_t)code;
                        ins3(s1, s2, s3, p);
                    }
                }
                #pragma unroll
                for (int off = 1; off <= 2; off <<= 1) {
                    unsigned long long o1 = __shfl_xor_sync(~0u, s1, off);
                    unsigned long long o2 = __shfl_xor_sync(~0u, s2, off);
                    unsigned long long o3 = __shfl_xor_sync(~0u, s3, off);
                    ins3(s1, s2, s3, o1);
                    ins3(s1, s2, s3, o2);
                    ins3(s1, s2, s3, o3);
                }
                ins3(rs1[h], rs2[h], rs3[h], s1);
                ins3(rs1[h], rs2[h], rs3[h], s2);
                ins3(rs1[h], rs2[h], rs3[h], s3);
            }
        }
    }

    if (tg == 0) {
        #pragma unroll
        for (int h = 0; h < 2; h++) {
            int node = node0 + wid * 16 + h * 8 + g;
            int c1 = (int)(rs1[h] & 0xFFFFFFFFu);
            g_idx[node] = c1;
            float f1 = funkey((uint32_t)(rs1[h] >> 32));
            float f2 = funkey((uint32_t)(rs2[h] >> 32));
            float f3 = funkey((uint32_t)(rs3[h] >> 32));
            if (!(f3 - f1 >= AM_MARGIN)) {
                int p = atomicAdd(&g_nflagB, 1);
                g_flagB[p] = node;
            } else if (!(f2 - f1 >= AM_MARGIN)) {
                int c2 = (int)(rs2[h] & 0xFFFFFFFFu);
                int p = atomicAdd(&g_nflagA, 1);
                g_flagA[p] = node;
                g_flagAC[p] = (c1 & 0xFFFF) | (c2 << 16);
            }
        }
    }
}

// ============================================================
// K5a: pairwise exact refine
// ============================================================
__global__ __launch_bounds__(256) void refineA(const float* __restrict__ x) {
    int lane = threadIdx.x & 31;
    int gw = (blockIdx.x * blockDim.x + threadIdx.x) >> 5;
    int nw = (gridDim.x * blockDim.x) >> 5;
    int n = g_nflagA;
    for (int f = gw; f < n; f += nw) {
        int node = g_flagA[f];
        int cc = g_flagAC[f];
        int c1 = cc & 0xFFFF, c2 = (cc >> 16) & 0xFFFF;
        const float4* xr = (const float4*)(x + (size_t)node * DD);
        const float4* b1 = (const float4*)(g_ccb + (size_t)c1 * DD);
        const float4* b2 = (const float4*)(g_ccb + (size_t)c2 * DD);
        float d1 = 0.f, d2 = 0.f;
        #pragma unroll
        for (int j = 0; j < 4; j++) {
            int q = lane + j * 32;
            float4 xv = xr[q], v1 = b1[q], v2 = b2[q];
            d1 += xv.x*v1.x + xv.y*v1.y + xv.z*v1.z + xv.w*v1.w;
            d2 += xv.x*v2.x + xv.y*v2.y + xv.z*v2.z + xv.w*v2.w;
        }
        #pragma unroll
        for (int off = 16; off; off >>= 1) {
            d1 += __shfl_xor_sync(~0u, d1, off);
            d2 += __shfl_xor_sync(~0u, d2, off);
        }
        if (lane == 0) {
            float s1 = g_cbn[c1] - 2.f * d1;
            float s2 = g_cbn[c2] - 2.f * d2;
            unsigned long long p1 = ((unsigned long long)fkey(s1) << 32) | (uint32_t)c1;
            unsigned long long p2 = ((unsigned long long)fkey(s2) << 32) | (uint32_t)c2;
            g_idx[node] = (int)(((p1 < p2) ? p1 : p2) & 0xFFFFFFFFu);
        }
    }
}

// ============================================================
// K5b: full-scan exact refine (3-way clusters)
// ============================================================
__global__ __launch_bounds__(256) void refineB(const float* __restrict__ x) {
    __shared__ __align__(16) float xs[DD];
    __shared__ unsigned long long sbest;
    int tid = threadIdx.x;
    int nf = g_nflagB;
    for (int f = blockIdx.x; f < nf; f += gridDim.x) {
        int node = g_flagB[f];
        if (tid < 128) ((float4*)xs)[tid] = ((const float4*)x)[(size_t)node * 128 + tid];
        if (tid == 0) sbest = ~0ULL;
        __syncthreads();
        unsigned long long best = ~0ULL;
        #pragma unroll
        for (int cc = 0; cc < 4; cc++) {
            int code = tid + cc * 256;
            const float4* cb = (const float4*)(g_ccb + (size_t)code * DD);
            float dot = 0.f;
            #pragma unroll 8
            for (int q = 0; q < 128; q++) {
                float4 a = ((const float4*)xs)[q], b = cb[q];
                dot += a.x * b.x + a.y * b.y + a.z * b.z + a.w * b.w;
            }
            float sc = g_cbn[code] - 2.f * dot;
            unsigned long long p = ((unsigned long long)fkey(sc) << 32) | (uint32_t)code;
            if (p < best) best = p;
        }
        atomicMin(&sbest, best);
        __syncthreads();
        if (tid == 0) g_idx[node] = (int)(sbest & 0xFFFFFFFFu);
        __syncthreads();
    }
}

// ============================================================
// K6: per node: x copy, z gather, inv norms
// ============================================================
__global__ void node_kernel(const float* __restrict__ x, float* __restrict__ out) {
    int n = blockIdx.x, t = threadIdx.x;
    float4 xv = ((const float4*)x)[(size_t)n*128 + t];
    ((float4*)(out + O_X))[(size_t)n*128 + t] = xv;
    int code = g_idx[n];
    float4 zv = ((const float4*)g_ct)[(size_t)code*128 + t];
    ((float4*)(out + O_Z))[(size_t)n*128 + t] = zv;
    float sx = xv.x*xv.x + xv.y*xv.y + xv.z*xv.z + xv.w*xv.w;
    float sz = zv.x*zv.x + zv.y*zv.y + zv.z*zv.z + zv.w*zv.w;
    #pragma unroll
    for (int off = 16; off; off >>= 1) {
        sx += __shfl_xor_sync(~0u, sx, off);
        sz += __shfl_xor_sync(~0u, sz, off);
    }
    __shared__ float rx[4], rz[4];
    if ((t & 31) == 0) { rx[t >> 5] = sx; rz[t >> 5] = sz; }
    __syncthreads();
    if (t == 0) {
        float nx = sqrtf(rx[0] + rx[1] + rx[2] + rx[3]);
        float nz = sqrtf(rz[0] + rz[1] + rz[2] + rz[3]);
        g_invnx[n] = 1.f / fmaxf(nx, 1e-12f);
        g_invnz[n] = 1.f / fmaxf(nz, 1e-12f);
    }
}

// ============================================================
// K7: pooled means + classifier heads
// ============================================================
__global__ __launch_bounds__(256) void pool_kernel(const float* __restrict__ x,
                                                   const float* __restrict__ clsw,
                                                   const float* __restrict__ clsb,
                                                   float* __restrict__ out) {
    int g = blockIdx.x, t = threadIdx.x;
    __shared__ int idxs[NPG];
    __shared__ float sp[3][DD];
    if (t < NPG) idxs[t] = g_idx[g*NPG + t];
    __syncthreads();
    for (int d = t; d < DD; d += 256) {
        float ax = 0.f, ac = 0.f, ak = 0.f;
        #pragma unroll 4
        for (int nn = 0; nn < NPG; nn++) {
            ax += x[(size_t)(g*NPG + nn)*DD + d];
            int c = idxs[nn];
            ac += g_ccb[(size_t)c*DD + d];
            ak += g_xcb[(size_t)c*DD + d];
        }
        float px = ax * (1.f/128.f);
        float pc = px + ac * (1.f/128.f);
        float pk = ak * (1.f/128.f);
        out[O_PX + (size_t)g*DD + d] = px;
        out[O_PC + (size_t)g*DD + d] = pc;
        sp[0][d] = pc; sp[1][d] = pk; sp[2][d] = px;
    }
    __syncthreads();
    int lane = t & 31, w = t >> 5;
    for (int job = w; job < 30; job += 8) {
        int vec = job / 10, cc = job % 10;
        float a = 0.f;
        for (int d = lane; d < DD; d += 32) a += sp[vec][d] * clsw[(size_t)cc*DD + d];
        #pragma unroll
        for (int off = 16; off; off >>= 1) a += __shfl_xor_sync(~0u, a, off);
        if (lane == 0) {
            long long base = (vec == 0) ? O_CPRE : (vec == 1 ? O_KPRE : O_YPRE);
            out[base + (size_t)g*TCLS + cc] = a + clsb[cc];
        }
    }
}

// ============================================================
// K8: adjacency via single-pass fp16 mma (Gram), normalize in epilogue.
// ============================================================
#define AJ_STAGE  SUB_TB
#define AJ_DYN    (2 * AJ_STAGE)

__device__ __forceinline__ void adj_stage(uint32_t dst, const __half* base, const int* idx_s,
                                          int node0, int mode, int kt) {
    int tid = threadIdx.x;
    #pragma unroll
    for (int it = 0; it < 4; it++) {
        int e = tid + it * 256;
        int row = e >> 3, c8 = e & 7;
        size_t roff = mode ? (size_t)idx_s[row] : (size_t)(node0 + row);
        cp_async16(dst + (uint32_t)row * RSTRIDE + (uint32_t)c8 * 16,
                   base + roff * DD + kt * 64 + c8 * 8);
    }
}

__global__ __launch_bounds__(256) void adj_mma(float* __restrict__ out) {
    extern __shared__ char sm[];
    __shared__ int s_v1;
    __shared__ int idx_s[NPG];
    __shared__ float invn_s[NPG];

    int tid = threadIdx.x, lane = tid & 31, wid = tid >> 5;
    int g = lane >> 2, tg = lane & 3;
    int b = blockIdx.x;
    int mode = b >> 9;
    int gr = b & 511;
    int node0 = gr * 128;

    int flags = mma_layout_probe(sm, &s_v1);
    int v1 = flags & 1;
    uint32_t offA1 = v1 ? 16u : (uint32_t)(8 * RSTRIDE);
    uint32_t offA2 = v1 ? (uint32_t)(8 * RSTRIDE) : 16u;

    if (tid < NPG) {
        idx_s[tid]  = g_idx[node0 + tid];
        invn_s[tid] = mode ? g_invnz[node0 + tid] : g_invnx[node0 + tid];
    }
    __syncthreads();

    const __half* base = mode ? g_ctf : g_xh;
    uint32_t smb = smem_u32(sm);

    adj_stage(smb, base, idx_s, node0, mode, 0);
    CP_COMMIT();

    float acc[16][4];
    #pragma unroll
    for (int nf = 0; nf < 16; nf++)
        #pragma unroll
        for (int q = 0; q < 4; q++) acc[nf][q] = 0.f;

    for (int kt = 0; kt < 8; kt++) {
        if (kt < 7) {
            adj_stage(smb + (uint32_t)((kt + 1) & 1) * AJ_STAGE, base, idx_s, node0, mode, kt + 1);
            CP_COMMIT();
            CP_WAIT(1);
        } else {
            CP_WAIT(0);
        }
        __syncthreads();

        const char* St = sm + (size_t)(kt & 1) * AJ_STAGE;
        const char* Ah = St + (size_t)(wid * 16 + g) * RSTRIDE;
        #pragma unroll
        for (int ks = 0; ks < 4; ks++) {
            int koff = (ks * 16 + tg * 2) * 2;
            uint32_t a0 = *(const uint32_t*)(Ah + koff);
            uint32_t a1 = *(const uint32_t*)(Ah + koff + offA1);
            uint32_t a2 = *(const uint32_t*)(Ah + koff + offA2);
            uint32_t a3 = *(const uint32_t*)(Ah + koff + 8 * RSTRIDE + 16);
            int kb = ks * 32 + tg * 4;
            #pragma unroll
            for (int nf = 0; nf < 16; nf++) {
                size_t bro = (size_t)(nf * 8 + g) * RSTRIDE + kb;
                uint32_t b0 = *(const uint32_t*)(St + bro);
                uint32_t b1 = *(const uint32_t*)(St + bro + 16);
                mma_f16(acc[nf], a0, a1, a2, a3, b0, b1);
            }
        }
        __syncthreads();
    }

    float* dst = out + (mode ? O_AR : O_AO) + (size_t)gr * (NPG * NPG);
    #pragma unroll
    for (int h = 0; h < 2; h++) {
        int r = wid * 16 + h * 8 + g;
        float invr = invn_s[r];
        #pragma unroll
        for (int nf = 0; nf < 16; nf++) {
            #pragma unroll
            for (int q = 0; q < 2; q++) {
                int c = nf * 8 + tg * 2 + q;
                dst[(size_t)r * NPG + c] = sigm10f(acc[nf][h * 2 + q] * invr * invn_s[c]);
            }
        }
    }
}

// ============================================================
extern "C" void kernel_launch(void* const* d_in, const int* in_sizes, int n_in,
                              void* d_out, int out_size) {
    const float* x      = (const float*)d_in[0];
    const float* cbin   = (const float*)d_in[2];
    const float* fc1w   = (const float*)d_in[3];
    const float* fc1b   = (const float*)d_in[4];
    const float* fc2w   = (const float*)d_in[5];
    const float* fc2b   = (const float*)d_in[6];
    const float* causal = (const float*)d_in[7];
    const float* clsw   = (const float*)d_in[8];
    const float* clsb   = (const float*)d_in[9];
    float* out = (float*)d_out;

    cudaFuncSetAttribute(argmin_mma3, cudaFuncAttributeMaxDynamicSharedMemorySize, SM3_DYN);
    cudaFuncSetAttribute(adj_mma,     cudaFuncAttributeMaxDynamicSharedMemorySize, AJ_DYN);

    diag_kernel<<<KC, 256>>>(causal, out);
    mlp_kernel<<<KC, 128>>>(cbin, fc1w, fc1b, fc2w, fc2b);
    gemm_cc<<<dim3(8, 32), 256>>>(causal, 3);           // fused: c1 + causal_cb
    cbn_kernel<<<KC, 128>>>();
    convert_cbct<<<(2 * C8) / 256, 256>>>();
    gemm_cc<<<dim3(8, 16), 256>>>(causal, 2);           // counter_cb
    convert_x<<<X8 / 256, 256>>>(x);
    argmin_mma3<<<NN / 128, 256, SM3_DYN>>>();
    refineA<<<64, 256>>>(x);
    refineB<<<64, 256>>>(x);
    node_kernel<<<NN, 128>>>(x, out);
    pool_kernel<<<GG, 256>>>(x, clsw, clsb, out);
    adj_mma<<<2 * GG, 256, AJ_DYN>>>(out);
}